// round 8
// baseline (speedup 1.0000x reference)
#include <cuda_runtime.h>
#include <cstdint>

#define Hh 192
#define Ww 192

__device__ float g_pooled[8 * 32];
__device__ float g_bias[8 * 32];

typedef unsigned long long ull;

__device__ __forceinline__ uint32_t cvt_tf32(float x) {
    uint32_t r; asm("cvt.rna.tf32.f32 %0, %1;" : "=r"(r) : "f"(x)); return r;
}
__device__ __forceinline__ void mma_tf32(float d[4], const uint32_t a[4], const uint32_t b[2]) {
    asm("mma.sync.aligned.m16n8k8.row.col.f32.tf32.tf32.f32 "
        "{%0,%1,%2,%3},{%4,%5,%6,%7},{%8,%9},{%0,%1,%2,%3};"
        : "+f"(d[0]), "+f"(d[1]), "+f"(d[2]), "+f"(d[3])
        : "r"(a[0]), "r"(a[1]), "r"(a[2]), "r"(a[3]), "r"(b[0]), "r"(b[1]));
}

// xs geometry: [q][yy][xx][8slots], row stride 148 floats, q-block 18*148=2664,
// half size 4*2664=10656. slot(n) = 2*(n&3) + ((n>>2)&1)  (pair (n, n+4) adjacent)
#define XROW 148
#define XQ   2664
#define XHALF 10656

// ---------------------------------------------------------------------------
// Kernel 1: global average pool — float4, 4 accumulators.
// ---------------------------------------------------------------------------
__global__ void pooled_kernel(const float* __restrict__ x) {
    int bn = blockIdx.x;
    const float4* p = (const float4*)(x + (size_t)bn * Hh * Ww);
    float4 a = make_float4(0.f, 0.f, 0.f, 0.f);
#pragma unroll 4
    for (int i = threadIdx.x; i < 9216; i += 256) {
        float4 v = p[i];
        a.x += v.x; a.y += v.y; a.z += v.z; a.w += v.w;
    }
    float s = (a.x + a.y) + (a.z + a.w);
#pragma unroll
    for (int o = 16; o > 0; o >>= 1) s += __shfl_xor_sync(0xffffffffu, s, o);
    __shared__ float red[8];
    if ((threadIdx.x & 31) == 0) red[threadIdx.x >> 5] = s;
    __syncthreads();
    if (threadIdx.x == 0) {
        float t = 0.f;
#pragma unroll
        for (int i = 0; i < 8; i++) t += red[i];
        g_pooled[bn] = t * (1.f / (Hh * Ww));
    }
}

// ---------------------------------------------------------------------------
// Kernel 2: bias MLP.
// ---------------------------------------------------------------------------
__global__ void bias_kernel(const float* __restrict__ b1w, const float* __restrict__ b1b,
                            const float* __restrict__ b2w, const float* __restrict__ b2b) {
    __shared__ float h[8 * 32];
    int t = threadIdx.x;
    int b = t >> 5, k = t & 31;
    float s = b1b[k];
    for (int n = 0; n < 32; n++) s += g_pooled[b * 32 + n] * b1w[k * 32 + n];
    h[t] = fmaxf(s, 0.f);
    __syncthreads();
    int m = k;
    float s2 = b2b[m];
    for (int kk = 0; kk < 32; kk++) s2 += h[b * 32 + kk] * b2w[m * 32 + kk];
    g_bias[t] = s2;
}

// ---------------------------------------------------------------------------
// Fused kernel: attention stack + main conv, 16x32 pair-tile per iteration.
// All fragment k-pairs (n, n+4) loaded as single LDS.64.
// ---------------------------------------------------------------------------
__global__ __launch_bounds__(512, 1)
void fused_kernel(const float* __restrict__ x, const float* __restrict__ a1w,
                  const float* __restrict__ a1b, const float* __restrict__ a2w,
                  const float* __restrict__ a2b, const float* __restrict__ a3w,
                  const float* __restrict__ a3b, const float* __restrict__ weight,
                  float* __restrict__ out) {
    extern __shared__ uint32_t smu[];
    uint32_t* xs = smu;                       // 2 * 10656 = 21312
    uint32_t* w1t = smu + 21312;              // 9*16*36 = 5184  [t][o16][n36 interleaved]
    uint32_t* ws = smu + 26496;               // 9*32*36 = 10368 [p][m][n36 interleaved]
    uint32_t* trbase = smu + 36864;           // 2 * 4608 (tr ull / atts float overlay)
    float* sbias = (float*)(smu + 46080);     // 32
    float* w2 = sbias + 32;                   // 81
    float* w3 = w2 + 81;                      // 81
    float* bb1 = w3 + 81;                     // 9
    float* bb2 = bb1 + 9;                     // 9
    float* bb3 = bb2 + 9;                     // 9

    int tid = threadIdx.x;

    // one-time weight fills (interleaved n-pairs: storage nn -> n = q*8+(s>>1)+4*(s&1))
    for (int i = tid; i < 5184; i += 512) {
        int t = i / 576;
        int r = i % 576;
        int o = r / 36, nn = r % 36;
        uint32_t v = 0u;
        if (o < 9 && nn < 32) {
            int n = (nn >> 3) * 8 + ((nn & 7) >> 1) + 4 * (nn & 1);
            v = cvt_tf32(a1w[o * 288 + n * 9 + t]);
        }
        w1t[i] = v;
    }
    for (int i = tid; i < 10368; i += 512) {
        int p = i / 1152;
        int r = i % 1152;
        int m = r / 36, nn = r % 36;
        uint32_t v = 0u;
        if (nn < 32) {
            int n = (nn >> 3) * 8 + ((nn & 7) >> 1) + 4 * (nn & 1);
            v = cvt_tf32(weight[(m * 32 + n) * 9 + p]);
        }
        ws[i] = v;
    }
    if (tid < 81) { w2[tid] = a2w[tid]; w3[tid] = a3w[tid]; }
    if (tid < 9) { bb1[tid] = a1b[tid]; bb2[tid] = a2b[tid]; bb3[tid] = a3b[tid]; }

    int wid = tid >> 5, lane = tid & 31;
    int r4 = lane >> 2, k0 = lane & 3;
    int tw = wid >> 3;              // warp's tile half
    int yA = 2 * (wid & 7);

    for (int it = 0; it < 4; it++) {
        int pairIdx = blockIdx.x * 4 + it;
        int b = pairIdx / 72;
        int rr = pairIdx % 72;
        int y0 = (rr / 6) * 16;
        int x0p = (rr % 6) * 32;

        __syncthreads();   // weights ready (it=0) / prev iter smem reads done

        // xs fill (div-free): thread -> (half, channel, row group), interleaved slots
        {
            int th = tid >> 8;
            int tid2 = tid & 255;
            int n = tid2 >> 3, s = tid2 & 7;
            int q = n >> 3;
            int slot = 2 * (n & 3) + ((n >> 2) & 1);
            int x0 = x0p + th * 16;
            const float* xb = x + (size_t)(b * 32 + n) * Hh * Ww;
            uint32_t* xst = xs + th * XHALF + q * XQ + slot;
            for (int yy = s; yy < 18; yy += 8) {
                int gy = y0 + yy - 1;
                bool yok = (unsigned)gy < Hh;
                uint32_t* row = xst + yy * XROW;
                const float* grow = xb + (size_t)gy * Ww + (x0 - 1);
#pragma unroll
                for (int xx = 0; xx < 18; xx++) {
                    int gx = x0 - 1 + xx;
                    float v = (yok && (unsigned)gx < Ww) ? grow[xx] : 0.f;
                    row[xx * 8] = cvt_tf32(v);
                }
            }
        }
        if (tid < 32) sbias[tid] = g_bias[b * 32 + tid];
        __syncthreads();

        const uint32_t* xsT = xs + tw * XHALF;

        // ---- attention mainloop (tf32 MMA) ----
        float DA[2][2][4];
#pragma unroll
        for (int f = 0; f < 2; f++)
#pragma unroll
            for (int oc = 0; oc < 2; oc++)
#pragma unroll
                for (int e = 0; e < 4; e++) DA[f][oc][e] = 0.f;

#pragma unroll
        for (int t = 0; t < 9; t++) {
            const int ki = t / 3, kj = t % 3;
            const uint32_t* wb = w1t + t * 576 + r4 * 36 + 2 * k0;
            int xoff = (yA + ki) * XROW + (r4 + kj) * 8 + 2 * k0;
#pragma unroll
            for (int q = 0; q < 4; q++) {
                const uint32_t* xc = xsT + q * XQ + xoff;
                uint2 A00 = *(const uint2*)(xc);
                uint2 A01 = *(const uint2*)(xc + 64);
                uint2 A10 = *(const uint2*)(xc + XROW);
                uint2 A11 = *(const uint2*)(xc + XROW + 64);
                uint32_t a0[4] = {A00.x, A01.x, A00.y, A01.y};
                uint32_t a1[4] = {A10.x, A11.x, A10.y, A11.y};
                const uint32_t* wq = wb + q * 8;
#pragma unroll
                for (int oc = 0; oc < 2; oc++) {
                    uint2 bv = *(const uint2*)(wq + oc * 288);
                    uint32_t bb[2] = {bv.x, bv.y};
                    mma_tf32(DA[0][oc], a0, bb);
                    mma_tf32(DA[1][oc], a1, bb);
                }
            }
        }

        // transpose DA -> tr (per-pixel o-pairs)
        {
            ull* tr = (ull*)(trbase + tw * 4608);
#pragma unroll
            for (int f = 0; f < 2; f++) {
                int yy = yA + f;
#pragma unroll
                for (int oc = 0; oc < 2; oc++) {
                    int pr = oc * 4 + k0;
                    float2 lo2 = make_float2(DA[f][oc][0], DA[f][oc][1]);
                    float2 hi2 = make_float2(DA[f][oc][2], DA[f][oc][3]);
                    tr[(yy * 16 + r4) * 9 + pr]     = *(ull*)&lo2;
                    tr[(yy * 16 + r4 + 8) * 9 + pr] = *(ull*)&hi2;
                }
            }
        }
        __syncthreads();

        // attention epilogue: one pixel per thread, exact fp32; atts overlays tr
        {
            int th = tid >> 8;
            int px = tid & 255;
            const ull* trt = (const ull*)(trbase + th * 4608);
            float u[10], z[9], att[9];
#pragma unroll
            for (int j = 0; j < 5; j++) {
                float2 v = *(float2*)&trt[px * 9 + j];
                u[2 * j] = v.x;
                u[2 * j + 1] = v.y;
            }
#pragma unroll
            for (int o = 0; o < 9; o++) u[o] = fmaxf(u[o] + bb1[o], 0.f);
#pragma unroll
            for (int o2 = 0; o2 < 9; o2++) {
                float s = bb2[o2];
#pragma unroll
                for (int o = 0; o < 9; o++) s += w2[o2 * 9 + o] * u[o];
                z[o2] = fmaxf(s, 0.f);
            }
#pragma unroll
            for (int o3 = 0; o3 < 9; o3++) {
                float s = bb3[o3];
#pragma unroll
                for (int o2 = 0; o2 < 9; o2++) s += w3[o3 * 9 + o2] * z[o2];
                att[o3] = 1.f / (1.f + __expf(-s));
            }
            __syncthreads();   // tr reads done before atts overlay writes
            float* atts_t = (float*)(trbase + th * 4608);   // [p][py][px]
#pragma unroll
            for (int o3 = 0; o3 < 9; o3++) atts_t[o3 * 256 + px] = att[o3];
        }
        __syncthreads();

        // ---- main mainloop (tf32 MMA + exact fp32 attention merge) ----
        const float* atts = (const float*)(trbase + tw * 4608);
        float D[2][4][4];
#pragma unroll
        for (int f = 0; f < 2; f++)
#pragma unroll
            for (int mc = 0; mc < 4; mc++)
#pragma unroll
                for (int e = 0; e < 4; e++) D[f][mc][e] = 0.f;

#pragma unroll
        for (int p = 0; p < 9; p++) {
            const int ki = p / 3, kj = p % 3;
            float G[2][4][4];
#pragma unroll
            for (int f = 0; f < 2; f++)
#pragma unroll
                for (int mc = 0; mc < 4; mc++)
#pragma unroll
                    for (int e = 0; e < 4; e++) G[f][mc][e] = 0.f;

            const uint32_t* wb = ws + p * 1152 + r4 * 36 + 2 * k0;
            int xoff = (yA + ki) * XROW + (r4 + kj) * 8 + 2 * k0;
#pragma unroll
            for (int q = 0; q < 4; q++) {
                const uint32_t* xc = xsT + q * XQ + xoff;
                uint2 A00 = *(const uint2*)(xc);
                uint2 A01 = *(const uint2*)(xc + 64);
                uint2 A10 = *(const uint2*)(xc + XROW);
                uint2 A11 = *(const uint2*)(xc + XROW + 64);
                uint32_t a0[4] = {A00.x, A01.x, A00.y, A01.y};
                uint32_t a1[4] = {A10.x, A11.x, A10.y, A11.y};
                const uint32_t* wq = wb + q * 8;
#pragma unroll
                for (int mc = 0; mc < 4; mc++) {
                    uint2 bv = *(const uint2*)(wq + mc * 288);
                    uint32_t bb[2] = {bv.x, bv.y};
                    mma_tf32(G[0][mc], a0, bb);
                    mma_tf32(G[1][mc], a1, bb);
                }
            }
#pragma unroll
            for (int f = 0; f < 2; f++) {
                int yy = yA + f;
                float attA = atts[p * 256 + yy * 16 + r4];
                float attB = atts[p * 256 + yy * 16 + r4 + 8];
#pragma unroll
                for (int mc = 0; mc < 4; mc++) {
                    D[f][mc][0] += attA * G[f][mc][0];
                    D[f][mc][1] += attA * G[f][mc][1];
                    D[f][mc][2] += attB * G[f][mc][2];
                    D[f][mc][3] += attB * G[f][mc][3];
                }
            }
        }

        // store
        {
            int x0 = x0p + tw * 16;
#pragma unroll
            for (int f = 0; f < 2; f++) {
                int gy = y0 + yA + f;
#pragma unroll
                for (int mc = 0; mc < 4; mc++) {
                    int m = mc * 8 + 2 * k0;
                    float bv0 = sbias[m], bv1 = sbias[m + 1];
                    float* o0 = out + ((size_t)(b * 32 + m) * Hh + gy) * Ww + x0;
                    float* o1 = o0 + (size_t)Hh * Ww;
                    o0[r4]     = D[f][mc][0] + bv0;
                    o1[r4]     = D[f][mc][1] + bv1;
                    o0[r4 + 8] = D[f][mc][2] + bv0;
                    o1[r4 + 8] = D[f][mc][3] + bv1;
                }
            }
        }
    }
}

// ---------------------------------------------------------------------------
extern "C" void kernel_launch(void* const* d_in, const int* in_sizes, int n_in,
                              void* d_out, int out_size) {
    const float* x   = (const float*)d_in[0];
    const float* a1w = (const float*)d_in[1];
    const float* a1b = (const float*)d_in[2];
    const float* a2w = (const float*)d_in[3];
    const float* a2b = (const float*)d_in[4];
    const float* a3w = (const float*)d_in[5];
    const float* a3b = (const float*)d_in[6];
    const float* b1w = (const float*)d_in[7];
    const float* b1b = (const float*)d_in[8];
    const float* b2w = (const float*)d_in[9];
    const float* b2b = (const float*)d_in[10];
    const float* wgt = (const float*)d_in[11];
    float* out = (float*)d_out;

    pooled_kernel<<<256, 256>>>(x);
    bias_kernel<<<1, 256>>>(b1w, b1b, b2w, b2b);

    int smF = (46080 + 32 + 81 + 81 + 9 + 9 + 9 + 3) * (int)sizeof(uint32_t);
    cudaFuncSetAttribute(fused_kernel, cudaFuncAttributeMaxDynamicSharedMemorySize, smF);
    fused_kernel<<<144, 512, smF>>>(x, a1w, a1b, a2w, a2b, a3w, a3b, wgt, out);
}

// round 9
// speedup vs baseline: 1.0830x; 1.0830x over previous
#include <cuda_runtime.h>
#include <cstdint>

#define Hh 192
#define Ww 192

__device__ float g_pooled[8 * 32];
__device__ float g_bias[8 * 32];

typedef unsigned long long ull;

__device__ __forceinline__ uint32_t cvt_tf32(float x) {
    uint32_t r; asm("cvt.rna.tf32.f32 %0, %1;" : "=r"(r) : "f"(x)); return r;
}
__device__ __forceinline__ void mma_tf32(float d[4], const uint32_t a[4], const uint32_t b[2]) {
    asm("mma.sync.aligned.m16n8k8.row.col.f32.tf32.tf32.f32 "
        "{%0,%1,%2,%3},{%4,%5,%6,%7},{%8,%9},{%0,%1,%2,%3};"
        : "+f"(d[0]), "+f"(d[1]), "+f"(d[2]), "+f"(d[3])
        : "r"(a[0]), "r"(a[1]), "r"(a[2]), "r"(a[3]), "r"(b[0]), "r"(b[1]));
}

// ---------------------------------------------------------------------------
// Kernel 1: global average pool — 1024 threads, 9 independent float4 loads.
// ---------------------------------------------------------------------------
__global__ __launch_bounds__(1024, 1)
void pooled_kernel(const float* __restrict__ x) {
    int bn = blockIdx.x;
    const float4* p = (const float4*)(x + (size_t)bn * Hh * Ww);
    int t = threadIdx.x;
    float4 v[9];
#pragma unroll
    for (int i = 0; i < 9; i++) v[i] = p[t + i * 1024];
    float s = 0.f;
#pragma unroll
    for (int i = 0; i < 9; i++) s += (v[i].x + v[i].y) + (v[i].z + v[i].w);
#pragma unroll
    for (int o = 16; o > 0; o >>= 1) s += __shfl_xor_sync(0xffffffffu, s, o);
    __shared__ float red[32];
    if ((t & 31) == 0) red[t >> 5] = s;
    __syncthreads();
    if (t < 32) {
        float r = red[t];
#pragma unroll
        for (int o = 16; o > 0; o >>= 1) r += __shfl_xor_sync(0xffffffffu, r, o);
        if (t == 0) g_pooled[bn] = r * (1.f / (Hh * Ww));
    }
}

// ---------------------------------------------------------------------------
// Kernel 2: bias MLP.
// ---------------------------------------------------------------------------
__global__ void bias_kernel(const float* __restrict__ b1w, const float* __restrict__ b1b,
                            const float* __restrict__ b2w, const float* __restrict__ b2b) {
    __shared__ float h[8 * 32];
    int t = threadIdx.x;
    int b = t >> 5, k = t & 31;
    float s = b1b[k];
    for (int n = 0; n < 32; n++) s += g_pooled[b * 32 + n] * b1w[k * 32 + n];
    h[t] = fmaxf(s, 0.f);
    __syncthreads();
    int m = k;
    float s2 = b2b[m];
    for (int kk = 0; kk < 32; kk++) s2 += h[b * 32 + kk] * b2w[m * 32 + kk];
    g_bias[t] = s2;
}

// ---------------------------------------------------------------------------
// Fused kernel (R7 layout): attention stack + main conv, 16x32 pair-tile.
// ---------------------------------------------------------------------------
__global__ __launch_bounds__(512, 1)
void fused_kernel(const float* __restrict__ x, const float* __restrict__ a1w,
                  const float* __restrict__ a1b, const float* __restrict__ a2w,
                  const float* __restrict__ a2b, const float* __restrict__ a3w,
                  const float* __restrict__ a3b, const float* __restrict__ weight,
                  float* __restrict__ out) {
    extern __shared__ uint32_t smu[];
    uint32_t* xs = smu;                     // 2 * 11520 = 23040
    uint32_t* w1t = smu + 23040;            // 9*16*36 = 5184  [t][o16][n36]
    uint32_t* ws = smu + 28224;             // 9*32*36 = 10368 [p][m][n36]
    uint32_t* trbase = smu + 38592;         // 2 * 4608 (tr ull / atts float overlay)
    float* sbias = (float*)(smu + 47808);   // 32
    float* w2 = sbias + 32;                 // 81
    float* w3 = w2 + 81;                    // 81
    float* bb1 = w3 + 81;                   // 9
    float* bb2 = bb1 + 9;                   // 9
    float* bb3 = bb2 + 9;                   // 9

    int tid = threadIdx.x;

    // one-time weight fills
    for (int i = tid; i < 5184; i += 512) {
        int t = i / 576;
        int r = i % 576;
        int o = r / 36, n = r % 36;
        w1t[i] = (o < 9 && n < 32) ? cvt_tf32(a1w[o * 288 + n * 9 + t]) : 0u;
    }
    for (int i = tid; i < 10368; i += 512) {
        int p = i / 1152;
        int r = i % 1152;
        int m = r / 36, n = r % 36;
        ws[i] = (n < 32) ? cvt_tf32(weight[(m * 32 + n) * 9 + p]) : 0u;
    }
    if (tid < 81) { w2[tid] = a2w[tid]; w3[tid] = a3w[tid]; }
    if (tid < 9) { bb1[tid] = a1b[tid]; bb2[tid] = a2b[tid]; bb3[tid] = a3b[tid]; }

    int wid = tid >> 5, lane = tid & 31;
    int r4 = lane >> 2, k0 = lane & 3;
    int tw = wid >> 3;              // warp's tile half
    int yA = 2 * (wid & 7);

    for (int it = 0; it < 4; it++) {
        int pairIdx = blockIdx.x * 4 + it;
        int b = pairIdx / 72;
        int rr = pairIdx % 72;
        int y0 = (rr / 6) * 16;
        int x0p = (rr % 6) * 32;

        __syncthreads();   // weights ready (it=0) / prev iter smem reads done

        // div-free xs fill
        {
            int th = tid >> 8;
            int tid2 = tid & 255;
            int n = tid2 >> 3, s = tid2 & 7;
            int x0 = x0p + th * 16;
            const float* xb = x + (size_t)(b * 32 + n) * Hh * Ww;
            uint32_t* xst = xs + th * 11520 + n * 360;
            for (int yy = s; yy < 18; yy += 8) {
                int gy = y0 + yy - 1;
                bool yok = (unsigned)gy < Hh;
                uint32_t* row = xst + yy * 20;
                const float* grow = xb + (size_t)gy * Ww + (x0 - 1);
#pragma unroll
                for (int xx = 0; xx < 18; xx++) {
                    int gx = x0 - 1 + xx;
                    float v = (yok && (unsigned)gx < Ww) ? grow[xx] : 0.f;
                    row[xx] = cvt_tf32(v);
                }
            }
        }
        if (tid < 32) sbias[tid] = g_bias[b * 32 + tid];
        __syncthreads();

        const uint32_t* xsT = xs + tw * 11520;

        // ---- attention mainloop (tf32 MMA) ----
        float DA[2][2][4];
#pragma unroll
        for (int f = 0; f < 2; f++)
#pragma unroll
            for (int oc = 0; oc < 2; oc++)
#pragma unroll
                for (int e = 0; e < 4; e++) DA[f][oc][e] = 0.f;

#pragma unroll
        for (int t = 0; t < 9; t++) {
            const int ki = t / 3, kj = t % 3;
            const uint32_t* wsT = w1t + t * 576;
            const uint32_t* xbase0 = xsT + k0 * 360 + (yA + ki) * 20 + r4 + kj;
            const uint32_t* xbase1 = xbase0 + 20;
#pragma unroll
            for (int q = 0; q < 4; q++) {
                const uint32_t* xc0 = xbase0 + q * 2880;
                const uint32_t* xc1 = xbase1 + q * 2880;
                uint32_t a0[4], a1[4];
                a0[0] = xc0[0];        a0[1] = xc0[8];
                a0[2] = xc0[4 * 360];  a0[3] = xc0[4 * 360 + 8];
                a1[0] = xc1[0];        a1[1] = xc1[8];
                a1[2] = xc1[4 * 360];  a1[3] = xc1[4 * 360 + 8];
                int n0 = 8 * q + k0;
                const uint32_t* wq = wsT + r4 * 36 + n0;
#pragma unroll
                for (int oc = 0; oc < 2; oc++) {
                    uint32_t bb[2];
                    bb[0] = wq[oc * 288];
                    bb[1] = wq[oc * 288 + 4];
                    mma_tf32(DA[0][oc], a0, bb);
                    mma_tf32(DA[1][oc], a1, bb);
                }
            }
        }

        // transpose DA -> tr (per-pixel o-pairs)
        {
            ull* tr = (ull*)(trbase + tw * 4608);
#pragma unroll
            for (int f = 0; f < 2; f++) {
                int yy = yA + f;
#pragma unroll
                for (int oc = 0; oc < 2; oc++) {
                    int pr = oc * 4 + k0;
                    float2 lo2 = make_float2(DA[f][oc][0], DA[f][oc][1]);
                    float2 hi2 = make_float2(DA[f][oc][2], DA[f][oc][3]);
                    tr[(yy * 16 + r4) * 9 + pr]     = *(ull*)&lo2;
                    tr[(yy * 16 + r4 + 8) * 9 + pr] = *(ull*)&hi2;
                }
            }
        }
        __syncthreads();

        // attention epilogue: one pixel per thread, exact fp32; atts overlays tr
        {
            int th = tid >> 8;
            int px = tid & 255;
            const ull* trt = (const ull*)(trbase + th * 4608);
            float u[10], z[9], att[9];
#pragma unroll
            for (int j = 0; j < 5; j++) {
                float2 v = *(float2*)&trt[px * 9 + j];
                u[2 * j] = v.x;
                u[2 * j + 1] = v.y;
            }
#pragma unroll
            for (int o = 0; o < 9; o++) u[o] = fmaxf(u[o] + bb1[o], 0.f);
#pragma unroll
            for (int o2 = 0; o2 < 9; o2++) {
                float s = bb2[o2];
#pragma unroll
                for (int o = 0; o < 9; o++) s += w2[o2 * 9 + o] * u[o];
                z[o2] = fmaxf(s, 0.f);
            }
#pragma unroll
            for (int o3 = 0; o3 < 9; o3++) {
                float s = bb3[o3];
#pragma unroll
                for (int o2 = 0; o2 < 9; o2++) s += w3[o3 * 9 + o2] * z[o2];
                att[o3] = 1.f / (1.f + __expf(-s));
            }
            __syncthreads();   // tr reads done before atts overlay writes
            float* atts_t = (float*)(trbase + th * 4608);   // [p][py][px]
#pragma unroll
            for (int o3 = 0; o3 < 9; o3++) atts_t[o3 * 256 + px] = att[o3];
        }
        __syncthreads();

        // ---- main mainloop (tf32 MMA + exact fp32 attention merge) ----
        const float* atts = (const float*)(trbase + tw * 4608);
        float D[2][4][4];
#pragma unroll
        for (int f = 0; f < 2; f++)
#pragma unroll
            for (int mc = 0; mc < 4; mc++)
#pragma unroll
                for (int e = 0; e < 4; e++) D[f][mc][e] = 0.f;

#pragma unroll
        for (int p = 0; p < 9; p++) {
            const int ki = p / 3, kj = p % 3;
            float G[2][4][4];
#pragma unroll
            for (int f = 0; f < 2; f++)
#pragma unroll
                for (int mc = 0; mc < 4; mc++)
#pragma unroll
                    for (int e = 0; e < 4; e++) G[f][mc][e] = 0.f;

            const uint32_t* wsP = ws + p * 1152;
            const uint32_t* xbase0 = xsT + k0 * 360 + (yA + ki) * 20 + r4 + kj;
            const uint32_t* xbase1 = xbase0 + 20;
#pragma unroll
            for (int q = 0; q < 4; q++) {
                const uint32_t* xc0 = xbase0 + q * 2880;
                const uint32_t* xc1 = xbase1 + q * 2880;
                uint32_t a0[4], a1[4];
                a0[0] = xc0[0];        a0[1] = xc0[8];
                a0[2] = xc0[4 * 360];  a0[3] = xc0[4 * 360 + 8];
                a1[0] = xc1[0];        a1[1] = xc1[8];
                a1[2] = xc1[4 * 360];  a1[3] = xc1[4 * 360 + 8];
                int n0 = 8 * q + k0;
                const uint32_t* wq = wsP + r4 * 36 + n0;
#pragma unroll
                for (int mc = 0; mc < 4; mc++) {
                    uint32_t bb[2];
                    bb[0] = wq[mc * 288];
                    bb[1] = wq[mc * 288 + 4];
                    mma_tf32(G[0][mc], a0, bb);
                    mma_tf32(G[1][mc], a1, bb);
                }
            }
#pragma unroll
            for (int f = 0; f < 2; f++) {
                int yy = yA + f;
                float attA = atts[p * 256 + yy * 16 + r4];
                float attB = atts[p * 256 + yy * 16 + r4 + 8];
#pragma unroll
                for (int mc = 0; mc < 4; mc++) {
                    D[f][mc][0] += attA * G[f][mc][0];
                    D[f][mc][1] += attA * G[f][mc][1];
                    D[f][mc][2] += attB * G[f][mc][2];
                    D[f][mc][3] += attB * G[f][mc][3];
                }
            }
        }

        // store
        {
            int x0 = x0p + tw * 16;
#pragma unroll
            for (int f = 0; f < 2; f++) {
                int gy = y0 + yA + f;
#pragma unroll
                for (int mc = 0; mc < 4; mc++) {
                    int m = mc * 8 + 2 * k0;
                    float bv0 = sbias[m], bv1 = sbias[m + 1];
                    float* o0 = out + ((size_t)(b * 32 + m) * Hh + gy) * Ww + x0;
                    float* o1 = o0 + (size_t)Hh * Ww;
                    o0[r4]     = D[f][mc][0] + bv0;
                    o1[r4]     = D[f][mc][1] + bv1;
                    o0[r4 + 8] = D[f][mc][2] + bv0;
                    o1[r4 + 8] = D[f][mc][3] + bv1;
                }
            }
        }
    }
}

// ---------------------------------------------------------------------------
extern "C" void kernel_launch(void* const* d_in, const int* in_sizes, int n_in,
                              void* d_out, int out_size) {
    const float* x   = (const float*)d_in[0];
    const float* a1w = (const float*)d_in[1];
    const float* a1b = (const float*)d_in[2];
    const float* a2w = (const float*)d_in[3];
    const float* a2b = (const float*)d_in[4];
    const float* a3w = (const float*)d_in[5];
    const float* a3b = (const float*)d_in[6];
    const float* b1w = (const float*)d_in[7];
    const float* b1b = (const float*)d_in[8];
    const float* b2w = (const float*)d_in[9];
    const float* b2b = (const float*)d_in[10];
    const float* wgt = (const float*)d_in[11];
    float* out = (float*)d_out;

    pooled_kernel<<<256, 1024>>>(x);
    bias_kernel<<<1, 256>>>(b1w, b1b, b2w, b2b);

    int smF = (47808 + 32 + 81 + 81 + 9 + 9 + 9 + 3) * (int)sizeof(uint32_t);
    cudaFuncSetAttribute(fused_kernel, cudaFuncAttributeMaxDynamicSharedMemorySize, smF);
    fused_kernel<<<144, 512, smF>>>(x, a1w, a1b, a2w, a2b, a3w, a3b, wgt, out);
}

// round 10
// speedup vs baseline: 1.0990x; 1.0147x over previous
#include <cuda_runtime.h>
#include <cstdint>

#define Hh 192
#define Ww 192

__device__ float g_part[768];
__device__ float g_bias[8 * 32];

typedef unsigned long long ull;

__device__ __forceinline__ uint32_t cvt_tf32(float x) {
    uint32_t r; asm("cvt.rna.tf32.f32 %0, %1;" : "=r"(r) : "f"(x)); return r;
}
__device__ __forceinline__ void mma_tf32(float d[4], const uint32_t a[4], const uint32_t b[2]) {
    asm("mma.sync.aligned.m16n8k8.row.col.f32.tf32.tf32.f32 "
        "{%0,%1,%2,%3},{%4,%5,%6,%7},{%8,%9},{%0,%1,%2,%3};"
        : "+f"(d[0]), "+f"(d[1]), "+f"(d[2]), "+f"(d[3])
        : "r"(a[0]), "r"(a[1]), "r"(a[2]), "r"(a[3]), "r"(b[0]), "r"(b[1]));
}

// ---------------------------------------------------------------------------
// Kernel 1: pooled partials — 768 CTAs (3 per (b,n)), 12 float4 per thread.
// ---------------------------------------------------------------------------
__global__ __launch_bounds__(256, 8)
void pooled_kernel(const float* __restrict__ x) {
    int blk = blockIdx.x;
    int bn = blk / 3, seg = blk % 3;
    const float4* p = (const float4*)x + (size_t)bn * 9216 + seg * 3072;
    int t = threadIdx.x;
    float4 v[12];
#pragma unroll
    for (int i = 0; i < 12; i++) v[i] = p[t + i * 256];
    float s = 0.f;
#pragma unroll
    for (int i = 0; i < 12; i++) s += (v[i].x + v[i].y) + (v[i].z + v[i].w);
#pragma unroll
    for (int o = 16; o > 0; o >>= 1) s += __shfl_xor_sync(0xffffffffu, s, o);
    __shared__ float red[8];
    if ((t & 31) == 0) red[t >> 5] = s;
    __syncthreads();
    if (t == 0) {
        float r = 0.f;
#pragma unroll
        for (int i = 0; i < 8; i++) r += red[i];
        g_part[blk] = r;
    }
}

// ---------------------------------------------------------------------------
// Kernel 2: bias MLP (sums pooled partials first).
// ---------------------------------------------------------------------------
__global__ void bias_kernel(const float* __restrict__ b1w, const float* __restrict__ b1b,
                            const float* __restrict__ b2w, const float* __restrict__ b2b) {
    __shared__ float ps[256];
    __shared__ float h[8 * 32];
    int t = threadIdx.x;
    ps[t] = (g_part[t * 3] + g_part[t * 3 + 1] + g_part[t * 3 + 2]) * (1.f / (Hh * Ww));
    __syncthreads();
    int b = t >> 5, k = t & 31;
    float s = b1b[k];
    for (int n = 0; n < 32; n++) s += ps[b * 32 + n] * b1w[k * 32 + n];
    h[t] = fmaxf(s, 0.f);
    __syncthreads();
    int m = k;
    float s2 = b2b[m];
    for (int kk = 0; kk < 32; kk++) s2 += h[b * 32 + kk] * b2w[m * 32 + kk];
    g_bias[t] = s2;
}

// ---------------------------------------------------------------------------
// Fused kernel: R7/R9 x-layout; weights in ull-pair layout (stride 20 ull)
// so every b-fragment is one conflict-free LDS.64.
//   ws2 ull[(p*32+m)*20 + 4q + k0] = {w[m][8q+k0][p], w[m][8q+k0+4][p]}
//   w1t2 ull[(t*16+o)*20 + 4q + k0] = {a1w[o][8q+k0][t], a1w[o][8q+k0+4][t]}
// ---------------------------------------------------------------------------
__global__ __launch_bounds__(512, 1)
void fused_kernel(const float* __restrict__ x, const float* __restrict__ a1w,
                  const float* __restrict__ a1b, const float* __restrict__ a2w,
                  const float* __restrict__ a2b, const float* __restrict__ a3w,
                  const float* __restrict__ a3b, const float* __restrict__ weight,
                  float* __restrict__ out) {
    extern __shared__ uint32_t smu[];
    uint32_t* xs = smu;                     // 2 * 11520 = 23040
    uint32_t* w1t2 = smu + 23040;           // 5760 u32 = 2880 ull
    uint32_t* ws2 = smu + 28800;            // 11520 u32 = 5760 ull
    uint32_t* trbase = smu + 40320;         // 2 * 4608
    float* sbias = (float*)(smu + 49536);   // 32
    float* w2 = sbias + 32;                 // 81
    float* w3 = w2 + 81;                    // 81
    float* bb1 = w3 + 81;                   // 9
    float* bb2 = bb1 + 9;                   // 9
    float* bb3 = bb2 + 9;                   // 9

    int tid = threadIdx.x;

    // one-time weight fills (ull-pair layout)
    for (int i = tid; i < 5760; i += 512) {
        int t = i / 640;
        int r = i % 640;
        int o = r / 40, c = r % 40;
        int pair = c >> 1, e = c & 1;
        uint32_t v = 0u;
        if (o < 9 && pair < 16) {
            int n = 8 * (pair >> 2) + (pair & 3) + 4 * e;
            v = cvt_tf32(a1w[o * 288 + n * 9 + t]);
        }
        w1t2[i] = v;
    }
    for (int i = tid; i < 11520; i += 512) {
        int p = i / 1280;
        int r = i % 1280;
        int m = r / 40, c = r % 40;
        int pair = c >> 1, e = c & 1;
        uint32_t v = 0u;
        if (pair < 16) {
            int n = 8 * (pair >> 2) + (pair & 3) + 4 * e;
            v = cvt_tf32(weight[(m * 32 + n) * 9 + p]);
        }
        ws2[i] = v;
    }
    if (tid < 81) { w2[tid] = a2w[tid]; w3[tid] = a3w[tid]; }
    if (tid < 9) { bb1[tid] = a1b[tid]; bb2[tid] = a2b[tid]; bb3[tid] = a3b[tid]; }

    int wid = tid >> 5, lane = tid & 31;
    int r4 = lane >> 2, k0 = lane & 3;
    int tw = wid >> 3;              // warp's tile half
    int yA = 2 * (wid & 7);

    const ull* w1u = (const ull*)w1t2;
    const ull* wsu = (const ull*)ws2;

    for (int it = 0; it < 4; it++) {
        int pairIdx = blockIdx.x * 4 + it;
        int b = pairIdx / 72;
        int rr = pairIdx % 72;
        int y0 = (rr / 6) * 16;
        int x0p = (rr % 6) * 32;

        __syncthreads();   // weights ready (it=0) / prev iter smem reads done

        // div-free xs fill
        {
            int th = tid >> 8;
            int tid2 = tid & 255;
            int n = tid2 >> 3, s = tid2 & 7;
            int x0 = x0p + th * 16;
            const float* xb = x + (size_t)(b * 32 + n) * Hh * Ww;
            uint32_t* xst = xs + th * 11520 + n * 360;
            for (int yy = s; yy < 18; yy += 8) {
                int gy = y0 + yy - 1;
                bool yok = (unsigned)gy < Hh;
                uint32_t* row = xst + yy * 20;
                const float* grow = xb + (size_t)gy * Ww + (x0 - 1);
#pragma unroll
                for (int xx = 0; xx < 18; xx++) {
                    int gx = x0 - 1 + xx;
                    float v = (yok && (unsigned)gx < Ww) ? grow[xx] : 0.f;
                    row[xx] = cvt_tf32(v);
                }
            }
        }
        if (tid < 32) sbias[tid] = g_bias[b * 32 + tid];
        __syncthreads();

        const uint32_t* xsT = xs + tw * 11520;

        // ---- attention mainloop (tf32 MMA) ----
        float DA[2][2][4];
#pragma unroll
        for (int f = 0; f < 2; f++)
#pragma unroll
            for (int oc = 0; oc < 2; oc++)
#pragma unroll
                for (int e = 0; e < 4; e++) DA[f][oc][e] = 0.f;

#pragma unroll
        for (int t = 0; t < 9; t++) {
            const int ki = t / 3, kj = t % 3;
            const ull* wbT = w1u + t * 320 + r4 * 20 + k0;
            const uint32_t* xbase0 = xsT + k0 * 360 + (yA + ki) * 20 + r4 + kj;
            const uint32_t* xbase1 = xbase0 + 20;
#pragma unroll
            for (int q = 0; q < 4; q++) {
                const uint32_t* xc0 = xbase0 + q * 2880;
                const uint32_t* xc1 = xbase1 + q * 2880;
                uint32_t a0[4], a1[4];
                a0[0] = xc0[0];        a0[1] = xc0[8];
                a0[2] = xc0[4 * 360];  a0[3] = xc0[4 * 360 + 8];
                a1[0] = xc1[0];        a1[1] = xc1[8];
                a1[2] = xc1[4 * 360];  a1[3] = xc1[4 * 360 + 8];
#pragma unroll
                for (int oc = 0; oc < 2; oc++) {
                    ull wv = wbT[oc * 160 + 4 * q];
                    uint32_t bb[2] = {(uint32_t)wv, (uint32_t)(wv >> 32)};
                    mma_tf32(DA[0][oc], a0, bb);
                    mma_tf32(DA[1][oc], a1, bb);
                }
            }
        }

        // transpose DA -> tr (per-pixel o-pairs)
        {
            ull* tr = (ull*)(trbase + tw * 4608);
#pragma unroll
            for (int f = 0; f < 2; f++) {
                int yy = yA + f;
#pragma unroll
                for (int oc = 0; oc < 2; oc++) {
                    int pr = oc * 4 + k0;
                    float2 lo2 = make_float2(DA[f][oc][0], DA[f][oc][1]);
                    float2 hi2 = make_float2(DA[f][oc][2], DA[f][oc][3]);
                    tr[(yy * 16 + r4) * 9 + pr]     = *(ull*)&lo2;
                    tr[(yy * 16 + r4 + 8) * 9 + pr] = *(ull*)&hi2;
                }
            }
        }
        __syncthreads();

        // attention epilogue: one pixel per thread, exact fp32; atts overlays tr
        {
            int th = tid >> 8;
            int px = tid & 255;
            const ull* trt = (const ull*)(trbase + th * 4608);
            float u[10], z[9], att[9];
#pragma unroll
            for (int j = 0; j < 5; j++) {
                float2 v = *(float2*)&trt[px * 9 + j];
                u[2 * j] = v.x;
                u[2 * j + 1] = v.y;
            }
#pragma unroll
            for (int o = 0; o < 9; o++) u[o] = fmaxf(u[o] + bb1[o], 0.f);
#pragma unroll
            for (int o2 = 0; o2 < 9; o2++) {
                float s = bb2[o2];
#pragma unroll
                for (int o = 0; o < 9; o++) s += w2[o2 * 9 + o] * u[o];
                z[o2] = fmaxf(s, 0.f);
            }
#pragma unroll
            for (int o3 = 0; o3 < 9; o3++) {
                float s = bb3[o3];
#pragma unroll
                for (int o2 = 0; o2 < 9; o2++) s += w3[o3 * 9 + o2] * z[o2];
                att[o3] = 1.f / (1.f + __expf(-s));
            }
            __syncthreads();   // tr reads done before atts overlay writes
            float* atts_t = (float*)(trbase + th * 4608);   // [p][py][px]
#pragma unroll
            for (int o3 = 0; o3 < 9; o3++) atts_t[o3 * 256 + px] = att[o3];
        }
        __syncthreads();

        // ---- main mainloop (tf32 MMA + exact fp32 attention merge) ----
        const float* atts = (const float*)(trbase + tw * 4608);
        float D[2][4][4];
#pragma unroll
        for (int f = 0; f < 2; f++)
#pragma unroll
            for (int mc = 0; mc < 4; mc++)
#pragma unroll
                for (int e = 0; e < 4; e++) D[f][mc][e] = 0.f;

#pragma unroll
        for (int p = 0; p < 9; p++) {
            const int ki = p / 3, kj = p % 3;
            float G[2][4][4];
#pragma unroll
            for (int f = 0; f < 2; f++)
#pragma unroll
                for (int mc = 0; mc < 4; mc++)
#pragma unroll
                    for (int e = 0; e < 4; e++) G[f][mc][e] = 0.f;

            const ull* wbP = wsu + p * 640 + r4 * 20 + k0;
            const uint32_t* xbase0 = xsT + k0 * 360 + (yA + ki) * 20 + r4 + kj;
            const uint32_t* xbase1 = xbase0 + 20;
#pragma unroll
            for (int q = 0; q < 4; q++) {
                const uint32_t* xc0 = xbase0 + q * 2880;
                const uint32_t* xc1 = xbase1 + q * 2880;
                uint32_t a0[4], a1[4];
                a0[0] = xc0[0];        a0[1] = xc0[8];
                a0[2] = xc0[4 * 360];  a0[3] = xc0[4 * 360 + 8];
                a1[0] = xc1[0];        a1[1] = xc1[8];
                a1[2] = xc1[4 * 360];  a1[3] = xc1[4 * 360 + 8];
#pragma unroll
                for (int mc = 0; mc < 4; mc++) {
                    ull wv = wbP[mc * 160 + 4 * q];
                    uint32_t bb[2] = {(uint32_t)wv, (uint32_t)(wv >> 32)};
                    mma_tf32(G[0][mc], a0, bb);
                    mma_tf32(G[1][mc], a1, bb);
                }
            }
#pragma unroll
            for (int f = 0; f < 2; f++) {
                int yy = yA + f;
                float attA = atts[p * 256 + yy * 16 + r4];
                float attB = atts[p * 256 + yy * 16 + r4 + 8];
#pragma unroll
                for (int mc = 0; mc < 4; mc++) {
                    D[f][mc][0] += attA * G[f][mc][0];
                    D[f][mc][1] += attA * G[f][mc][1];
                    D[f][mc][2] += attB * G[f][mc][2];
                    D[f][mc][3] += attB * G[f][mc][3];
                }
            }
        }

        // store
        {
            int x0 = x0p + tw * 16;
#pragma unroll
            for (int f = 0; f < 2; f++) {
                int gy = y0 + yA + f;
#pragma unroll
                for (int mc = 0; mc < 4; mc++) {
                    int m = mc * 8 + 2 * k0;
                    float bv0 = sbias[m], bv1 = sbias[m + 1];
                    float* o0 = out + ((size_t)(b * 32 + m) * Hh + gy) * Ww + x0;
                    float* o1 = o0 + (size_t)Hh * Ww;
                    o0[r4]     = D[f][mc][0] + bv0;
                    o1[r4]     = D[f][mc][1] + bv1;
                    o0[r4 + 8] = D[f][mc][2] + bv0;
                    o1[r4 + 8] = D[f][mc][3] + bv1;
                }
            }
        }
    }
}

// ---------------------------------------------------------------------------
extern "C" void kernel_launch(void* const* d_in, const int* in_sizes, int n_in,
                              void* d_out, int out_size) {
    const float* x   = (const float*)d_in[0];
    const float* a1w = (const float*)d_in[1];
    const float* a1b = (const float*)d_in[2];
    const float* a2w = (const float*)d_in[3];
    const float* a2b = (const float*)d_in[4];
    const float* a3w = (const float*)d_in[5];
    const float* a3b = (const float*)d_in[6];
    const float* b1w = (const float*)d_in[7];
    const float* b1b = (const float*)d_in[8];
    const float* b2w = (const float*)d_in[9];
    const float* b2b = (const float*)d_in[10];
    const float* wgt = (const float*)d_in[11];
    float* out = (float*)d_out;

    pooled_kernel<<<768, 256>>>(x);
    bias_kernel<<<1, 256>>>(b1w, b1b, b2w, b2b);

    int smF = (49536 + 32 + 81 + 81 + 9 + 9 + 9 + 3) * (int)sizeof(uint32_t);
    cudaFuncSetAttribute(fused_kernel, cudaFuncAttributeMaxDynamicSharedMemorySize, smF);
    fused_kernel<<<144, 512, smF>>>(x, a1w, a1b, a2w, a2b, a3w, a3b, wgt, out);
}

// round 11
// speedup vs baseline: 1.2702x; 1.1558x over previous
#include <cuda_runtime.h>
#include <cstdint>

#define Hh 192
#define Ww 192

// padded raw-f32 copy of x: [b*32+n][194 rows][208 cols], col = gx+4, row = gy+1
#define PSTRIDE 208
#define PPLANE  40352   // 194*208
__device__ float g_xt[256 * PPLANE];
__device__ float g_part[256];
__device__ float g_bias[8 * 32];

typedef unsigned long long ull;

__device__ __forceinline__ uint32_t cvt_tf32(float x) {
    uint32_t r; asm("cvt.rna.tf32.f32 %0, %1;" : "=r"(r) : "f"(x)); return r;
}
__device__ __forceinline__ void mma_tf32(float d[4], const uint32_t a[4], const uint32_t b[2]) {
    asm("mma.sync.aligned.m16n8k8.row.col.f32.tf32.tf32.f32 "
        "{%0,%1,%2,%3},{%4,%5,%6,%7},{%8,%9},{%0,%1,%2,%3};"
        : "+f"(d[0]), "+f"(d[1]), "+f"(d[2]), "+f"(d[3])
        : "r"(a[0]), "r"(a[1]), "r"(a[2]), "r"(a[3]), "r"(b[0]), "r"(b[1]));
}

// ---------------------------------------------------------------------------
// Kernel 1: prep — padded copy of x + pooled partial sums (one pass).
// ---------------------------------------------------------------------------
__global__ __launch_bounds__(256, 4)
void prep_kernel(const float* __restrict__ x) {
    int plane = blockIdx.x;   // b*32+n
    const float4* src = (const float4*)(x + (size_t)plane * (Hh * Ww));
    float* dst = g_xt + (size_t)plane * PPLANE;
    int t = threadIdx.x;

    float s = 0.f;
#pragma unroll 4
    for (int k = 0; k < 36; k++) {
        int i = t + k * 256;
        float4 v = src[i];
        int gy = i / 48, gx4 = i % 48;
        *(float4*)(dst + (gy + 1) * PSTRIDE + 4 + gx4 * 4) = v;
        s += (v.x + v.y) + (v.z + v.w);
    }
    // zero top/bottom rows (rows 0, 193): 52 float4 each
    for (int i = t; i < 104; i += 256) {
        int row = (i < 52) ? 0 : 193;
        int c4 = (i < 52) ? i : i - 52;
        *(float4*)(dst + row * PSTRIDE + c4 * 4) = make_float4(0.f, 0.f, 0.f, 0.f);
    }
    // zero side cols for rows 1..192: col4 {0, 49, 50, 51}
    for (int i = t; i < 768; i += 256) {
        int row = 1 + (i >> 2);
        int c4sel = i & 3;
        int c4 = (c4sel == 0) ? 0 : (48 + c4sel);
        *(float4*)(dst + row * PSTRIDE + c4 * 4) = make_float4(0.f, 0.f, 0.f, 0.f);
    }

#pragma unroll
    for (int o = 16; o > 0; o >>= 1) s += __shfl_xor_sync(0xffffffffu, s, o);
    __shared__ float red[8];
    if ((t & 31) == 0) red[t >> 5] = s;
    __syncthreads();
    if (t == 0) {
        float r = 0.f;
#pragma unroll
        for (int i = 0; i < 8; i++) r += red[i];
        g_part[plane] = r;
    }
}

// ---------------------------------------------------------------------------
// Kernel 2: bias MLP.
// ---------------------------------------------------------------------------
__global__ void bias_kernel(const float* __restrict__ b1w, const float* __restrict__ b1b,
                            const float* __restrict__ b2w, const float* __restrict__ b2b) {
    __shared__ float ps[256];
    __shared__ float h[8 * 32];
    int t = threadIdx.x;
    ps[t] = g_part[t] * (1.f / (Hh * Ww));
    __syncthreads();
    int b = t >> 5, k = t & 31;
    float s = b1b[k];
    for (int n = 0; n < 32; n++) s += ps[b * 32 + n] * b1w[k * 32 + n];
    h[t] = fmaxf(s, 0.f);
    __syncthreads();
    int m = k;
    float s2 = b2b[m];
    for (int kk = 0; kk < 32; kk++) s2 += h[b * 32 + kk] * b2w[m * 32 + kk];
    g_bias[t] = s2;
}

// ---------------------------------------------------------------------------
// Fused kernel: xs holds RAW f32 (cvt in fragment path). Attention applied by
// scaling the A-fragment (round(x*att) -> tf32), accumulating straight into D.
// Weights remain tf32 ull-pairs (one LDS.64 per b-fragment).
// ---------------------------------------------------------------------------
__global__ __launch_bounds__(512, 1)
void fused_kernel(const float* __restrict__ a1w, const float* __restrict__ a1b,
                  const float* __restrict__ a2w, const float* __restrict__ a2b,
                  const float* __restrict__ a3w, const float* __restrict__ a3b,
                  const float* __restrict__ weight, float* __restrict__ out) {
    extern __shared__ uint32_t smu[];
    uint32_t* xs = smu;                     // 2 * 11520 (raw f32 bits)
    uint32_t* w1t2 = smu + 23040;           // 5760 u32 = 2880 ull
    uint32_t* ws2 = smu + 28800;            // 11520 u32 = 5760 ull
    uint32_t* trbase = smu + 40320;         // 2 * 4608
    float* sbias = (float*)(smu + 49536);   // 32
    float* w2 = sbias + 32;                 // 81
    float* w3 = w2 + 81;                    // 81
    float* bb1 = w3 + 81;                   // 9
    float* bb2 = bb1 + 9;                   // 9
    float* bb3 = bb2 + 9;                   // 9

    int tid = threadIdx.x;

    // one-time weight fills (ull-pair tf32 layout)
    for (int i = tid; i < 5760; i += 512) {
        int t = i / 640;
        int r = i % 640;
        int o = r / 40, c = r % 40;
        int pair = c >> 1, e = c & 1;
        uint32_t v = 0u;
        if (o < 9 && pair < 16) {
            int n = 8 * (pair >> 2) + (pair & 3) + 4 * e;
            v = cvt_tf32(a1w[o * 288 + n * 9 + t]);
        }
        w1t2[i] = v;
    }
    for (int i = tid; i < 11520; i += 512) {
        int p = i / 1280;
        int r = i % 1280;
        int m = r / 40, c = r % 40;
        int pair = c >> 1, e = c & 1;
        uint32_t v = 0u;
        if (pair < 16) {
            int n = 8 * (pair >> 2) + (pair & 3) + 4 * e;
            v = cvt_tf32(weight[(m * 32 + n) * 9 + p]);
        }
        ws2[i] = v;
    }
    if (tid < 81) { w2[tid] = a2w[tid]; w3[tid] = a3w[tid]; }
    if (tid < 9) { bb1[tid] = a1b[tid]; bb2[tid] = a2b[tid]; bb3[tid] = a3b[tid]; }

    int wid = tid >> 5, lane = tid & 31;
    int r4 = lane >> 2, k0 = lane & 3;
    int tw = wid >> 3;
    int yA = 2 * (wid & 7);

    const ull* w1u = (const ull*)w1t2;
    const ull* wsu = (const ull*)ws2;

    for (int it = 0; it < 4; it++) {
        int pairIdx = blockIdx.x * 4 + it;
        int b = pairIdx / 72;
        int rr = pairIdx % 72;
        int y0 = (rr / 6) * 16;
        int x0p = (rr % 6) * 32;

        __syncthreads();

        // xs fill from padded buffer: no bounds checks, no cvt.
        for (int r = tid; r < 1152; r += 512) {
            int th = r >= 576;
            int rw = th ? (r - 576) : r;
            int n = rw / 18, yy = rw % 18;
            int x0 = x0p + th * 16;
            const float* src = g_xt + (size_t)(b * 32 + n) * PPLANE + (y0 + yy) * PSTRIDE + x0;
            uint32_t* drow = xs + th * 11520 + n * 360 + yy * 20;
            drow[0] = __float_as_uint(src[3]);
#pragma unroll
            for (int k = 0; k < 5; k++) {
                float4 v = *(const float4*)(src + 4 + 4 * k);
                int xx = 4 * k + 1;
                drow[xx] = __float_as_uint(v.x);
                drow[xx + 1] = __float_as_uint(v.y);
                drow[xx + 2] = __float_as_uint(v.z);
                if (k < 4) drow[xx + 3] = __float_as_uint(v.w);
            }
        }
        if (tid < 32) sbias[tid] = g_bias[b * 32 + tid];
        __syncthreads();

        const uint32_t* xsT = xs + tw * 11520;

        // ---- attention mainloop: cvt raw->tf32 on A, MMA into DA ----
        float DA[2][2][4];
#pragma unroll
        for (int f = 0; f < 2; f++)
#pragma unroll
            for (int oc = 0; oc < 2; oc++)
#pragma unroll
                for (int e = 0; e < 4; e++) DA[f][oc][e] = 0.f;

#pragma unroll
        for (int t = 0; t < 9; t++) {
            const int ki = t / 3, kj = t % 3;
            const ull* wbT = w1u + t * 320 + r4 * 20 + k0;
            const uint32_t* xbase0 = xsT + k0 * 360 + (yA + ki) * 20 + r4 + kj;
            const uint32_t* xbase1 = xbase0 + 20;
#pragma unroll
            for (int q = 0; q < 4; q++) {
                const uint32_t* xc0 = xbase0 + q * 2880;
                const uint32_t* xc1 = xbase1 + q * 2880;
                uint32_t a0[4], a1[4];
                a0[0] = cvt_tf32(__uint_as_float(xc0[0]));
                a0[1] = cvt_tf32(__uint_as_float(xc0[8]));
                a0[2] = cvt_tf32(__uint_as_float(xc0[4 * 360]));
                a0[3] = cvt_tf32(__uint_as_float(xc0[4 * 360 + 8]));
                a1[0] = cvt_tf32(__uint_as_float(xc1[0]));
                a1[1] = cvt_tf32(__uint_as_float(xc1[8]));
                a1[2] = cvt_tf32(__uint_as_float(xc1[4 * 360]));
                a1[3] = cvt_tf32(__uint_as_float(xc1[4 * 360 + 8]));
#pragma unroll
                for (int oc = 0; oc < 2; oc++) {
                    ull wv = wbT[oc * 160 + 4 * q];
                    uint32_t bb[2] = {(uint32_t)wv, (uint32_t)(wv >> 32)};
                    mma_tf32(DA[0][oc], a0, bb);
                    mma_tf32(DA[1][oc], a1, bb);
                }
            }
        }

        // transpose DA -> tr
        {
            ull* tr = (ull*)(trbase + tw * 4608);
#pragma unroll
            for (int f = 0; f < 2; f++) {
                int yy = yA + f;
#pragma unroll
                for (int oc = 0; oc < 2; oc++) {
                    int pr = oc * 4 + k0;
                    float2 lo2 = make_float2(DA[f][oc][0], DA[f][oc][1]);
                    float2 hi2 = make_float2(DA[f][oc][2], DA[f][oc][3]);
                    tr[(yy * 16 + r4) * 9 + pr]     = *(ull*)&lo2;
                    tr[(yy * 16 + r4 + 8) * 9 + pr] = *(ull*)&hi2;
                }
            }
        }
        __syncthreads();

        // attention epilogue (exact fp32), atts overlays tr
        {
            int th = tid >> 8;
            int px = tid & 255;
            const ull* trt = (const ull*)(trbase + th * 4608);
            float u[10], z[9], att[9];
#pragma unroll
            for (int j = 0; j < 5; j++) {
                float2 v = *(float2*)&trt[px * 9 + j];
                u[2 * j] = v.x;
                u[2 * j + 1] = v.y;
            }
#pragma unroll
            for (int o = 0; o < 9; o++) u[o] = fmaxf(u[o] + bb1[o], 0.f);
#pragma unroll
            for (int o2 = 0; o2 < 9; o2++) {
                float s = bb2[o2];
#pragma unroll
                for (int o = 0; o < 9; o++) s += w2[o2 * 9 + o] * u[o];
                z[o2] = fmaxf(s, 0.f);
            }
#pragma unroll
            for (int o3 = 0; o3 < 9; o3++) {
                float s = bb3[o3];
#pragma unroll
                for (int o2 = 0; o2 < 9; o2++) s += w3[o3 * 9 + o2] * z[o2];
                att[o3] = 1.f / (1.f + __expf(-s));
            }
            __syncthreads();
            float* atts_t = (float*)(trbase + th * 4608);
#pragma unroll
            for (int o3 = 0; o3 < 9; o3++) atts_t[o3 * 256 + px] = att[o3];
        }
        __syncthreads();

        // ---- main mainloop: scale A by att, round once, MMA into D ----
        const float* atts = (const float*)(trbase + tw * 4608);
        float D[2][4][4];
#pragma unroll
        for (int f = 0; f < 2; f++)
#pragma unroll
            for (int mc = 0; mc < 4; mc++)
#pragma unroll
                for (int e = 0; e < 4; e++) D[f][mc][e] = 0.f;

#pragma unroll
        for (int p = 0; p < 9; p++) {
            const int ki = p / 3, kj = p % 3;
            float attA0 = atts[p * 256 + yA * 16 + r4];
            float attB0 = atts[p * 256 + yA * 16 + r4 + 8];
            float attA1 = atts[p * 256 + (yA + 1) * 16 + r4];
            float attB1 = atts[p * 256 + (yA + 1) * 16 + r4 + 8];
            const ull* wbP = wsu + p * 640 + r4 * 20 + k0;
            const uint32_t* xbase0 = xsT + k0 * 360 + (yA + ki) * 20 + r4 + kj;
            const uint32_t* xbase1 = xbase0 + 20;
#pragma unroll
            for (int q = 0; q < 4; q++) {
                const uint32_t* xc0 = xbase0 + q * 2880;
                const uint32_t* xc1 = xbase1 + q * 2880;
                uint32_t a0[4], a1[4];
                a0[0] = cvt_tf32(__uint_as_float(xc0[0]) * attA0);
                a0[1] = cvt_tf32(__uint_as_float(xc0[8]) * attB0);
                a0[2] = cvt_tf32(__uint_as_float(xc0[4 * 360]) * attA0);
                a0[3] = cvt_tf32(__uint_as_float(xc0[4 * 360 + 8]) * attB0);
                a1[0] = cvt_tf32(__uint_as_float(xc1[0]) * attA1);
                a1[1] = cvt_tf32(__uint_as_float(xc1[8]) * attB1);
                a1[2] = cvt_tf32(__uint_as_float(xc1[4 * 360]) * attA1);
                a1[3] = cvt_tf32(__uint_as_float(xc1[4 * 360 + 8]) * attB1);
#pragma unroll
                for (int mc = 0; mc < 4; mc++) {
                    ull wv = wbP[mc * 160 + 4 * q];
                    uint32_t bb[2] = {(uint32_t)wv, (uint32_t)(wv >> 32)};
                    mma_tf32(D[0][mc], a0, bb);
                    mma_tf32(D[1][mc], a1, bb);
                }
            }
        }

        // store
        {
            int x0 = x0p + tw * 16;
#pragma unroll
            for (int f = 0; f < 2; f++) {
                int gy = y0 + yA + f;
#pragma unroll
                for (int mc = 0; mc < 4; mc++) {
                    int m = mc * 8 + 2 * k0;
                    float bv0 = sbias[m], bv1 = sbias[m + 1];
                    float* o0 = out + ((size_t)(b * 32 + m) * Hh + gy) * Ww + x0;
                    float* o1 = o0 + (size_t)Hh * Ww;
                    o0[r4]     = D[f][mc][0] + bv0;
                    o1[r4]     = D[f][mc][1] + bv1;
                    o0[r4 + 8] = D[f][mc][2] + bv0;
                    o1[r4 + 8] = D[f][mc][3] + bv1;
                }
            }
        }
    }
}

// ---------------------------------------------------------------------------
extern "C" void kernel_launch(void* const* d_in, const int* in_sizes, int n_in,
                              void* d_out, int out_size) {
    const float* x   = (const float*)d_in[0];
    const float* a1w = (const float*)d_in[1];
    const float* a1b = (const float*)d_in[2];
    const float* a2w = (const float*)d_in[3];
    const float* a2b = (const float*)d_in[4];
    const float* a3w = (const float*)d_in[5];
    const float* a3b = (const float*)d_in[6];
    const float* b1w = (const float*)d_in[7];
    const float* b1b = (const float*)d_in[8];
    const float* b2w = (const float*)d_in[9];
    const float* b2b = (const float*)d_in[10];
    const float* wgt = (const float*)d_in[11];
    float* out = (float*)d_out;

    prep_kernel<<<256, 256>>>(x);
    bias_kernel<<<1, 256>>>(b1w, b1b, b2w, b2b);

    int smF = (49536 + 32 + 81 + 81 + 9 + 9 + 9 + 3) * (int)sizeof(uint32_t);
    cudaFuncSetAttribute(fused_kernel, cudaFuncAttributeMaxDynamicSharedMemorySize, smF);
    fused_kernel<<<144, 512, smF>>>(a1w, a1b, a2w, a2b, a3w, a3b, wgt, out);
}

// round 12
// speedup vs baseline: 1.2783x; 1.0064x over previous
#include <cuda_runtime.h>
#include <cstdint>

#define Hh 192
#define Ww 192

// padded raw-f32 copy of x: [b*32+n][194 rows][208 cols], col = gx+4, row = gy+1
#define PSTRIDE 208
#define PPLANE  40352   // 194*208
__device__ float g_xt[256 * PPLANE];
__device__ float g_part[512];
__device__ float g_bias[8 * 32];

// xs geometry (u32): row stride 24, n-stride 456 (19 rows; 456%32==8 keeps
// fragment lane addr 8*k0+r4 conflict-free), half = 32*456
#define XR 24
#define XN 456
#define XH 14592

typedef unsigned long long ull;

__device__ __forceinline__ uint32_t cvt_tf32(float x) {
    uint32_t r; asm("cvt.rna.tf32.f32 %0, %1;" : "=r"(r) : "f"(x)); return r;
}
__device__ __forceinline__ void mma_tf32(float d[4], const uint32_t a[4], const uint32_t b[2]) {
    asm("mma.sync.aligned.m16n8k8.row.col.f32.tf32.tf32.f32 "
        "{%0,%1,%2,%3},{%4,%5,%6,%7},{%8,%9},{%0,%1,%2,%3};"
        : "+f"(d[0]), "+f"(d[1]), "+f"(d[2]), "+f"(d[3])
        : "r"(a[0]), "r"(a[1]), "r"(a[2]), "r"(a[3]), "r"(b[0]), "r"(b[1]));
}
__device__ __forceinline__ void cpasync16(uint32_t dst_sh, const void* src) {
    asm volatile("cp.async.cg.shared.global [%0], [%1], 16;" :: "r"(dst_sh), "l"(src));
}

// ---------------------------------------------------------------------------
// Kernel 1: prep — padded copy + pooled partials. 2 CTAs per plane.
// ---------------------------------------------------------------------------
__global__ __launch_bounds__(256, 8)
void prep_kernel(const float* __restrict__ x) {
    int blk = blockIdx.x;
    int plane = blk >> 1, half = blk & 1;
    const float4* src = (const float4*)(x + (size_t)plane * (Hh * Ww));
    float* dst = g_xt + (size_t)plane * PPLANE;
    int t = threadIdx.x;

    float s = 0.f;
#pragma unroll 3
    for (int k = 0; k < 18; k++) {
        int i = half * 4608 + t + k * 256;      // float4 index in plane
        float4 v = src[i];
        int gy = i / 48, gx4 = i % 48;
        *(float4*)(dst + (gy + 1) * PSTRIDE + 4 + gx4 * 4) = v;
        s += (v.x + v.y) + (v.z + v.w);
    }
    // zero top (half 0) / bottom (half 1) padding row: 52 float4
    if (t < 52) {
        int row = half ? 193 : 0;
        *(float4*)(dst + row * PSTRIDE + t * 4) = make_float4(0.f, 0.f, 0.f, 0.f);
    }
    // zero side cols for this half's 96 rows: col4 {0, 49, 50, 51}
    for (int i = t; i < 384; i += 256) {
        int row = 1 + half * 96 + (i >> 2);
        int c4sel = i & 3;
        int c4 = (c4sel == 0) ? 0 : (48 + c4sel);
        *(float4*)(dst + row * PSTRIDE + c4 * 4) = make_float4(0.f, 0.f, 0.f, 0.f);
    }

#pragma unroll
    for (int o = 16; o > 0; o >>= 1) s += __shfl_xor_sync(0xffffffffu, s, o);
    __shared__ float red[8];
    if ((t & 31) == 0) red[t >> 5] = s;
    __syncthreads();
    if (t == 0) {
        float r = 0.f;
#pragma unroll
        for (int i = 0; i < 8; i++) r += red[i];
        g_part[blk] = r;
    }
}

// ---------------------------------------------------------------------------
// Kernel 2: bias MLP.
// ---------------------------------------------------------------------------
__global__ void bias_kernel(const float* __restrict__ b1w, const float* __restrict__ b1b,
                            const float* __restrict__ b2w, const float* __restrict__ b2b) {
    __shared__ float ps[256];
    __shared__ float h[8 * 32];
    int t = threadIdx.x;
    ps[t] = (g_part[2 * t] + g_part[2 * t + 1]) * (1.f / (Hh * Ww));
    __syncthreads();
    int b = t >> 5, k = t & 31;
    float s = b1b[k];
    for (int n = 0; n < 32; n++) s += ps[b * 32 + n] * b1w[k * 32 + n];
    h[t] = fmaxf(s, 0.f);
    __syncthreads();
    int m = k;
    float s2 = b2b[m];
    for (int kk = 0; kk < 32; kk++) s2 += h[b * 32 + kk] * b2w[m * 32 + kk];
    g_bias[t] = s2;
}

// ---------------------------------------------------------------------------
// Fused kernel: cp.async xs fill (6x LDGSTS.128 per row, no regs), raw-f32 xs,
// att applied on A-fragment, tf32 MMA straight into D.
// ---------------------------------------------------------------------------
__global__ __launch_bounds__(512, 1)
void fused_kernel(const float* __restrict__ a1w, const float* __restrict__ a1b,
                  const float* __restrict__ a2w, const float* __restrict__ a2b,
                  const float* __restrict__ a3w, const float* __restrict__ a3b,
                  const float* __restrict__ weight, float* __restrict__ out) {
    extern __shared__ uint32_t smu[];
    uint32_t* xs = smu;                     // 2 * XH = 29184 (raw f32 bits)
    uint32_t* w1t2 = smu + 29184;           // 5760
    uint32_t* ws2 = smu + 34944;            // 11520
    uint32_t* trbase = smu + 46464;         // 2 * 4608
    float* sbias = (float*)(smu + 55680);   // 32
    float* w2 = sbias + 32;                 // 81
    float* w3 = w2 + 81;                    // 81
    float* bb1 = w3 + 81;                   // 9
    float* bb2 = bb1 + 9;                   // 9
    float* bb3 = bb2 + 9;                   // 9

    int tid = threadIdx.x;
    uint32_t xs_sh = (uint32_t)__cvta_generic_to_shared(xs);

    // one-time weight fills (ull-pair tf32 layout)
    for (int i = tid; i < 5760; i += 512) {
        int t = i / 640;
        int r = i % 640;
        int o = r / 40, c = r % 40;
        int pair = c >> 1, e = c & 1;
        uint32_t v = 0u;
        if (o < 9 && pair < 16) {
            int n = 8 * (pair >> 2) + (pair & 3) + 4 * e;
            v = cvt_tf32(a1w[o * 288 + n * 9 + t]);
        }
        w1t2[i] = v;
    }
    for (int i = tid; i < 11520; i += 512) {
        int p = i / 1280;
        int r = i % 1280;
        int m = r / 40, c = r % 40;
        int pair = c >> 1, e = c & 1;
        uint32_t v = 0u;
        if (pair < 16) {
            int n = 8 * (pair >> 2) + (pair & 3) + 4 * e;
            v = cvt_tf32(weight[(m * 32 + n) * 9 + p]);
        }
        ws2[i] = v;
    }
    if (tid < 81) { w2[tid] = a2w[tid]; w3[tid] = a3w[tid]; }
    if (tid < 9) { bb1[tid] = a1b[tid]; bb2[tid] = a2b[tid]; bb3[tid] = a3b[tid]; }

    int wid = tid >> 5, lane = tid & 31;
    int r4 = lane >> 2, k0 = lane & 3;
    int tw = wid >> 3;
    int yA = 2 * (wid & 7);

    const ull* w1u = (const ull*)w1t2;
    const ull* wsu = (const ull*)ws2;

    for (int it = 0; it < 4; it++) {
        int pairIdx = blockIdx.x * 4 + it;
        int b = pairIdx / 72;
        int rr = pairIdx % 72;
        int y0 = (rr / 6) * 16;
        int x0p = (rr % 6) * 32;

        __syncthreads();

        // xs fill: 24-float aligned row copies via cp.async (1152 rows)
        for (int r = tid; r < 1152; r += 512) {
            int th = r >= 576;
            int rw = r - th * 576;
            int n = rw / 18, yy = rw - n * 18;
            int x0 = x0p + th * 16;
            const float* src = g_xt + (size_t)(b * 32 + n) * PPLANE + (y0 + yy) * PSTRIDE + x0;
            uint32_t dsh = xs_sh + 4u * (th * XH + n * XN + yy * XR);
#pragma unroll
            for (int k = 0; k < 6; k++) cpasync16(dsh + 16 * k, src + 4 * k);
        }
        asm volatile("cp.async.commit_group;");
        if (tid < 32) sbias[tid] = g_bias[b * 32 + tid];
        asm volatile("cp.async.wait_group 0;");
        __syncthreads();

        const uint32_t* xsT = xs + tw * XH;

        // ---- attention mainloop: cvt raw->tf32 on A, MMA into DA ----
        float DA[2][2][4];
#pragma unroll
        for (int f = 0; f < 2; f++)
#pragma unroll
            for (int oc = 0; oc < 2; oc++)
#pragma unroll
                for (int e = 0; e < 4; e++) DA[f][oc][e] = 0.f;

#pragma unroll
        for (int t = 0; t < 9; t++) {
            const int ki = t / 3, kj = t % 3;
            const ull* wbT = w1u + t * 320 + r4 * 20 + k0;
            const uint32_t* xbase0 = xsT + k0 * XN + (yA + ki) * XR + (r4 + kj) + 3;
            const uint32_t* xbase1 = xbase0 + XR;
#pragma unroll
            for (int q = 0; q < 4; q++) {
                const uint32_t* xc0 = xbase0 + q * (8 * XN);
                const uint32_t* xc1 = xbase1 + q * (8 * XN);
                uint32_t a0[4], a1[4];
                a0[0] = cvt_tf32(__uint_as_float(xc0[0]));
                a0[1] = cvt_tf32(__uint_as_float(xc0[8]));
                a0[2] = cvt_tf32(__uint_as_float(xc0[4 * XN]));
                a0[3] = cvt_tf32(__uint_as_float(xc0[4 * XN + 8]));
                a1[0] = cvt_tf32(__uint_as_float(xc1[0]));
                a1[1] = cvt_tf32(__uint_as_float(xc1[8]));
                a1[2] = cvt_tf32(__uint_as_float(xc1[4 * XN]));
                a1[3] = cvt_tf32(__uint_as_float(xc1[4 * XN + 8]));
#pragma unroll
                for (int oc = 0; oc < 2; oc++) {
                    ull wv = wbT[oc * 160 + 4 * q];
                    uint32_t bb[2] = {(uint32_t)wv, (uint32_t)(wv >> 32)};
                    mma_tf32(DA[0][oc], a0, bb);
                    mma_tf32(DA[1][oc], a1, bb);
                }
            }
        }

        // transpose DA -> tr
        {
            ull* tr = (ull*)(trbase + tw * 4608);
#pragma unroll
            for (int f = 0; f < 2; f++) {
                int yy = yA + f;
#pragma unroll
                for (int oc = 0; oc < 2; oc++) {
                    int pr = oc * 4 + k0;
                    float2 lo2 = make_float2(DA[f][oc][0], DA[f][oc][1]);
                    float2 hi2 = make_float2(DA[f][oc][2], DA[f][oc][3]);
                    tr[(yy * 16 + r4) * 9 + pr]     = *(ull*)&lo2;
                    tr[(yy * 16 + r4 + 8) * 9 + pr] = *(ull*)&hi2;
                }
            }
        }
        __syncthreads();

        // attention epilogue (exact fp32), atts overlays tr
        {
            int th = tid >> 8;
            int px = tid & 255;
            const ull* trt = (const ull*)(trbase + th * 4608);
            float u[10], z[9], att[9];
#pragma unroll
            for (int j = 0; j < 5; j++) {
                float2 v = *(float2*)&trt[px * 9 + j];
                u[2 * j] = v.x;
                u[2 * j + 1] = v.y;
            }
#pragma unroll
            for (int o = 0; o < 9; o++) u[o] = fmaxf(u[o] + bb1[o], 0.f);
#pragma unroll
            for (int o2 = 0; o2 < 9; o2++) {
                float s = bb2[o2];
#pragma unroll
                for (int o = 0; o < 9; o++) s += w2[o2 * 9 + o] * u[o];
                z[o2] = fmaxf(s, 0.f);
            }
#pragma unroll
            for (int o3 = 0; o3 < 9; o3++) {
                float s = bb3[o3];
#pragma unroll
                for (int o2 = 0; o2 < 9; o2++) s += w3[o3 * 9 + o2] * z[o2];
                att[o3] = 1.f / (1.f + __expf(-s));
            }
            __syncthreads();
            float* atts_t = (float*)(trbase + th * 4608);
#pragma unroll
            for (int o3 = 0; o3 < 9; o3++) atts_t[o3 * 256 + px] = att[o3];
        }
        __syncthreads();

        // ---- main mainloop: scale A by att, round once, MMA into D ----
        const float* atts = (const float*)(trbase + tw * 4608);
        float D[2][4][4];
#pragma unroll
        for (int f = 0; f < 2; f++)
#pragma unroll
            for (int mc = 0; mc < 4; mc++)
#pragma unroll
                for (int e = 0; e < 4; e++) D[f][mc][e] = 0.f;

#pragma unroll
        for (int p = 0; p < 9; p++) {
            const int ki = p / 3, kj = p % 3;
            float attA0 = atts[p * 256 + yA * 16 + r4];
            float attB0 = atts[p * 256 + yA * 16 + r4 + 8];
            float attA1 = atts[p * 256 + (yA + 1) * 16 + r4];
            float attB1 = atts[p * 256 + (yA + 1) * 16 + r4 + 8];
            const ull* wbP = wsu + p * 640 + r4 * 20 + k0;
            const uint32_t* xbase0 = xsT + k0 * XN + (yA + ki) * XR + (r4 + kj) + 3;
            const uint32_t* xbase1 = xbase0 + XR;
#pragma unroll
            for (int q = 0; q < 4; q++) {
                const uint32_t* xc0 = xbase0 + q * (8 * XN);
                const uint32_t* xc1 = xbase1 + q * (8 * XN);
                uint32_t a0[4], a1[4];
                a0[0] = cvt_tf32(__uint_as_float(xc0[0]) * attA0);
                a0[1] = cvt_tf32(__uint_as_float(xc0[8]) * attB0);
                a0[2] = cvt_tf32(__uint_as_float(xc0[4 * XN]) * attA0);
                a0[3] = cvt_tf32(__uint_as_float(xc0[4 * XN + 8]) * attB0);
                a1[0] = cvt_tf32(__uint_as_float(xc1[0]) * attA1);
                a1[1] = cvt_tf32(__uint_as_float(xc1[8]) * attB1);
                a1[2] = cvt_tf32(__uint_as_float(xc1[4 * XN]) * attA1);
                a1[3] = cvt_tf32(__uint_as_float(xc1[4 * XN + 8]) * attB1);
#pragma unroll
                for (int mc = 0; mc < 4; mc++) {
                    ull wv = wbP[mc * 160 + 4 * q];
                    uint32_t bb[2] = {(uint32_t)wv, (uint32_t)(wv >> 32)};
                    mma_tf32(D[0][mc], a0, bb);
                    mma_tf32(D[1][mc], a1, bb);
                }
            }
        }

        // store
        {
            int x0 = x0p + tw * 16;
#pragma unroll
            for (int f = 0; f < 2; f++) {
                int gy = y0 + yA + f;
#pragma unroll
                for (int mc = 0; mc < 4; mc++) {
                    int m = mc * 8 + 2 * k0;
                    float bv0 = sbias[m], bv1 = sbias[m + 1];
                    float* o0 = out + ((size_t)(b * 32 + m) * Hh + gy) * Ww + x0;
                    float* o1 = o0 + (size_t)Hh * Ww;
                    o0[r4]     = D[f][mc][0] + bv0;
                    o1[r4]     = D[f][mc][1] + bv1;
                    o0[r4 + 8] = D[f][mc][2] + bv0;
                    o1[r4 + 8] = D[f][mc][3] + bv1;
                }
            }
        }
    }
}

// ---------------------------------------------------------------------------
extern "C" void kernel_launch(void* const* d_in, const int* in_sizes, int n_in,
                              void* d_out, int out_size) {
    const float* x   = (const float*)d_in[0];
    const float* a1w = (const float*)d_in[1];
    const float* a1b = (const float*)d_in[2];
    const float* a2w = (const float*)d_in[3];
    const float* a2b = (const float*)d_in[4];
    const float* a3w = (const float*)d_in[5];
    const float* a3b = (const float*)d_in[6];
    const float* b1w = (const float*)d_in[7];
    const float* b1b = (const float*)d_in[8];
    const float* b2w = (const float*)d_in[9];
    const float* b2b = (const float*)d_in[10];
    const float* wgt = (const float*)d_in[11];
    float* out = (float*)d_out;

    prep_kernel<<<512, 256>>>(x);
    bias_kernel<<<1, 256>>>(b1w, b1b, b2w, b2b);

    int smF = (55680 + 32 + 81 + 81 + 9 + 9 + 9 + 3) * (int)sizeof(uint32_t);
    cudaFuncSetAttribute(fused_kernel, cudaFuncAttributeMaxDynamicSharedMemorySize, smF);
    fused_kernel<<<144, 512, smF>>>(a1w, a1b, a2w, a2b, a3w, a3b, wgt, out);
}

// round 13
// speedup vs baseline: 1.2954x; 1.0133x over previous
#include <cuda_runtime.h>
#include <cstdint>

#define Hh 192
#define Ww 192

// padded tf32-rounded copy of x: [b*32+n][194 rows][208 cols], col = gx+4, row = gy+1
#define PSTRIDE 208
#define PPLANE  40352   // 194*208
__device__ float g_xt[256 * PPLANE];
__device__ float g_part[512];
__device__ float g_bias[8 * 32];

// xs geometry (u32): row stride 24, n-stride 456, half = 32*456
#define XR 24
#define XN 456
#define XH 14592

typedef unsigned long long ull;

__device__ __forceinline__ uint32_t cvt_tf32(float x) {
    uint32_t r; asm("cvt.rna.tf32.f32 %0, %1;" : "=r"(r) : "f"(x)); return r;
}
__device__ __forceinline__ void mma_tf32(float d[4], const uint32_t a[4], const uint32_t b[2]) {
    asm("mma.sync.aligned.m16n8k8.row.col.f32.tf32.tf32.f32 "
        "{%0,%1,%2,%3},{%4,%5,%6,%7},{%8,%9},{%0,%1,%2,%3};"
        : "+f"(d[0]), "+f"(d[1]), "+f"(d[2]), "+f"(d[3])
        : "r"(a[0]), "r"(a[1]), "r"(a[2]), "r"(a[3]), "r"(b[0]), "r"(b[1]));
}
__device__ __forceinline__ void cpasync16(uint32_t dst_sh, const void* src) {
    asm volatile("cp.async.cg.shared.global [%0], [%1], 16;" :: "r"(dst_sh), "l"(src));
}
__device__ __forceinline__ void barh(int th) {
    asm volatile("bar.sync %0, %1;" :: "r"(th + 1), "r"(256) : "memory");
}

// ---------------------------------------------------------------------------
// Kernel 1: prep — padded tf32 copy + raw pooled partials. 2 CTAs per plane.
// ---------------------------------------------------------------------------
__global__ __launch_bounds__(256, 8)
void prep_kernel(const float* __restrict__ x) {
    int blk = blockIdx.x;
    int plane = blk >> 1, half = blk & 1;
    const float4* src = (const float4*)(x + (size_t)plane * (Hh * Ww));
    uint32_t* dst = (uint32_t*)(g_xt + (size_t)plane * PPLANE);
    int t = threadIdx.x;

    float s = 0.f;
#pragma unroll 3
    for (int k = 0; k < 18; k++) {
        int i = half * 4608 + t + k * 256;
        float4 v = src[i];
        s += (v.x + v.y) + (v.z + v.w);
        uint4 w;
        w.x = cvt_tf32(v.x); w.y = cvt_tf32(v.y);
        w.z = cvt_tf32(v.z); w.w = cvt_tf32(v.w);
        int gy = i / 48, gx4 = i % 48;
        *(uint4*)(dst + (gy + 1) * PSTRIDE + 4 + gx4 * 4) = w;
    }
    if (t < 52) {
        int row = half ? 193 : 0;
        *(uint4*)(dst + row * PSTRIDE + t * 4) = make_uint4(0u, 0u, 0u, 0u);
    }
    for (int i = t; i < 384; i += 256) {
        int row = 1 + half * 96 + (i >> 2);
        int c4sel = i & 3;
        int c4 = (c4sel == 0) ? 0 : (48 + c4sel);
        *(uint4*)(dst + row * PSTRIDE + c4 * 4) = make_uint4(0u, 0u, 0u, 0u);
    }

#pragma unroll
    for (int o = 16; o > 0; o >>= 1) s += __shfl_xor_sync(0xffffffffu, s, o);
    __shared__ float red[8];
    if ((t & 31) == 0) red[t >> 5] = s;
    __syncthreads();
    if (t == 0) {
        float r = 0.f;
#pragma unroll
        for (int i = 0; i < 8; i++) r += red[i];
        g_part[blk] = r;
    }
}

// ---------------------------------------------------------------------------
// Kernel 2: bias MLP.
// ---------------------------------------------------------------------------
__global__ void bias_kernel(const float* __restrict__ b1w, const float* __restrict__ b1b,
                            const float* __restrict__ b2w, const float* __restrict__ b2b) {
    __shared__ float ps[256];
    __shared__ float h[8 * 32];
    int t = threadIdx.x;
    ps[t] = (g_part[2 * t] + g_part[2 * t + 1]) * (1.f / (Hh * Ww));
    __syncthreads();
    int b = t >> 5, k = t & 31;
    float s = b1b[k];
    for (int n = 0; n < 32; n++) s += ps[b * 32 + n] * b1w[k * 32 + n];
    h[t] = fmaxf(s, 0.f);
    __syncthreads();
    int m = k;
    float s2 = b2b[m];
    for (int kk = 0; kk < 32; kk++) s2 += h[b * 32 + kk] * b2w[m * 32 + kk];
    g_bias[t] = s2;
}

// ---------------------------------------------------------------------------
// Fused kernel: two independent 256-thread halves with per-half named
// barriers (phase drift => memory/compute overlap). xs holds tf32 bits
// (no cvt in attn loop). Attention applied on A-fragment in main loop.
// ---------------------------------------------------------------------------
__global__ __launch_bounds__(512, 1)
void fused_kernel(const float* __restrict__ a1w, const float* __restrict__ a1b,
                  const float* __restrict__ a2w, const float* __restrict__ a2b,
                  const float* __restrict__ a3w, const float* __restrict__ a3b,
                  const float* __restrict__ weight, float* __restrict__ out) {
    extern __shared__ uint32_t smu[];
    uint32_t* xs = smu;                     // 2 * XH = 29184 (tf32 bits)
    uint32_t* w1t2 = smu + 29184;           // 5760
    uint32_t* ws2 = smu + 34944;            // 11520
    uint32_t* trbase = smu + 46464;         // 2 * 4608
    float* sbias = (float*)(smu + 55680);   // 64 (per-half copies)
    float* w2 = sbias + 64;                 // 81
    float* w3 = w2 + 81;                    // 81
    float* bb1 = w3 + 81;                   // 9
    float* bb2 = bb1 + 9;                   // 9
    float* bb3 = bb2 + 9;                   // 9

    int tid = threadIdx.x;
    uint32_t xs_sh = (uint32_t)__cvta_generic_to_shared(xs);

    // one-time weight fills (ull-pair tf32 layout)
    for (int i = tid; i < 5760; i += 512) {
        int t = i / 640;
        int r = i % 640;
        int o = r / 40, c = r % 40;
        int pair = c >> 1, e = c & 1;
        uint32_t v = 0u;
        if (o < 9 && pair < 16) {
            int n = 8 * (pair >> 2) + (pair & 3) + 4 * e;
            v = cvt_tf32(a1w[o * 288 + n * 9 + t]);
        }
        w1t2[i] = v;
    }
    for (int i = tid; i < 11520; i += 512) {
        int p = i / 1280;
        int r = i % 1280;
        int m = r / 40, c = r % 40;
        int pair = c >> 1, e = c & 1;
        uint32_t v = 0u;
        if (pair < 16) {
            int n = 8 * (pair >> 2) + (pair & 3) + 4 * e;
            v = cvt_tf32(weight[(m * 32 + n) * 9 + p]);
        }
        ws2[i] = v;
    }
    if (tid < 81) { w2[tid] = a2w[tid]; w3[tid] = a3w[tid]; }
    if (tid < 9) { bb1[tid] = a1b[tid]; bb2[tid] = a2b[tid]; bb3[tid] = a3b[tid]; }
    __syncthreads();

    int wid = tid >> 5, lane = tid & 31;
    int r4 = lane >> 2, k0 = lane & 3;
    int th = wid >> 3;              // half id (matches tid>=256)
    int tloc = tid & 255;
    int yA = 2 * (wid & 7);

    const ull* w1u = (const ull*)w1t2;
    const ull* wsu = (const ull*)ws2;
    const uint32_t* xsT = xs + th * XH;

    for (int it = 0; it < 4; it++) {
        int pairIdx = blockIdx.x * 4 + it;
        int b = pairIdx / 72;
        int rr = pairIdx % 72;
        int y0 = (rr / 6) * 16;
        int x0 = (rr % 6) * 32 + th * 16;

        barh(th);   // prev iter's reads (this half) done before refill

        // per-half xs fill via cp.async (576 rows of 24 floats)
        for (int r = tloc; r < 576; r += 256) {
            int n = r / 18, yy = r - n * 18;
            const float* src = g_xt + (size_t)(b * 32 + n) * PPLANE + (y0 + yy) * PSTRIDE + x0;
            uint32_t dsh = xs_sh + 4u * (th * XH + n * XN + yy * XR);
#pragma unroll
            for (int k = 0; k < 6; k++) cpasync16(dsh + 16 * k, src + 4 * k);
        }
        asm volatile("cp.async.commit_group;");
        if (tloc < 32) sbias[th * 32 + tloc] = g_bias[b * 32 + tloc];
        asm volatile("cp.async.wait_group 0;");
        barh(th);

        // ---- attention mainloop: xs already tf32, straight to MMA ----
        float DA[2][2][4];
#pragma unroll
        for (int f = 0; f < 2; f++)
#pragma unroll
            for (int oc = 0; oc < 2; oc++)
#pragma unroll
                for (int e = 0; e < 4; e++) DA[f][oc][e] = 0.f;

#pragma unroll
        for (int t = 0; t < 9; t++) {
            const int ki = t / 3, kj = t % 3;
            const ull* wbT = w1u + t * 320 + r4 * 20 + k0;
            const uint32_t* xbase0 = xsT + k0 * XN + (yA + ki) * XR + (r4 + kj) + 3;
            const uint32_t* xbase1 = xbase0 + XR;
#pragma unroll
            for (int q = 0; q < 4; q++) {
                const uint32_t* xc0 = xbase0 + q * (8 * XN);
                const uint32_t* xc1 = xbase1 + q * (8 * XN);
                uint32_t a0[4] = {xc0[0], xc0[8], xc0[4 * XN], xc0[4 * XN + 8]};
                uint32_t a1[4] = {xc1[0], xc1[8], xc1[4 * XN], xc1[4 * XN + 8]};
#pragma unroll
                for (int oc = 0; oc < 2; oc++) {
                    ull wv = wbT[oc * 160 + 4 * q];
                    uint32_t bb[2] = {(uint32_t)wv, (uint32_t)(wv >> 32)};
                    mma_tf32(DA[0][oc], a0, bb);
                    mma_tf32(DA[1][oc], a1, bb);
                }
            }
        }

        // transpose DA -> tr (per-half region)
        {
            ull* tr = (ull*)(trbase + th * 4608);
#pragma unroll
            for (int f = 0; f < 2; f++) {
                int yy = yA + f;
#pragma unroll
                for (int oc = 0; oc < 2; oc++) {
                    int pr = oc * 4 + k0;
                    float2 lo2 = make_float2(DA[f][oc][0], DA[f][oc][1]);
                    float2 hi2 = make_float2(DA[f][oc][2], DA[f][oc][3]);
                    tr[(yy * 16 + r4) * 9 + pr]     = *(ull*)&lo2;
                    tr[(yy * 16 + r4 + 8) * 9 + pr] = *(ull*)&hi2;
                }
            }
        }
        barh(th);

        // attention epilogue (exact fp32): one pixel per thread of this half
        {
            int px = tloc;
            const ull* trt = (const ull*)(trbase + th * 4608);
            float u[10], z[9], att[9];
#pragma unroll
            for (int j = 0; j < 5; j++) {
                float2 v = *(float2*)&trt[px * 9 + j];
                u[2 * j] = v.x;
                u[2 * j + 1] = v.y;
            }
#pragma unroll
            for (int o = 0; o < 9; o++) u[o] = fmaxf(u[o] + bb1[o], 0.f);
#pragma unroll
            for (int o2 = 0; o2 < 9; o2++) {
                float s = bb2[o2];
#pragma unroll
                for (int o = 0; o < 9; o++) s += w2[o2 * 9 + o] * u[o];
                z[o2] = fmaxf(s, 0.f);
            }
#pragma unroll
            for (int o3 = 0; o3 < 9; o3++) {
                float s = bb3[o3];
#pragma unroll
                for (int o2 = 0; o2 < 9; o2++) s += w3[o3 * 9 + o2] * z[o2];
                att[o3] = 1.f / (1.f + __expf(-s));
            }
            barh(th);   // tr reads done before atts overlay
            float* atts_t = (float*)(trbase + th * 4608);
#pragma unroll
            for (int o3 = 0; o3 < 9; o3++) atts_t[o3 * 256 + px] = att[o3];
        }
        barh(th);

        // ---- main mainloop: scale A by att, round, MMA into D ----
        const float* atts = (const float*)(trbase + th * 4608);
        float D[2][4][4];
#pragma unroll
        for (int f = 0; f < 2; f++)
#pragma unroll
            for (int mc = 0; mc < 4; mc++)
#pragma unroll
                for (int e = 0; e < 4; e++) D[f][mc][e] = 0.f;

#pragma unroll
        for (int p = 0; p < 9; p++) {
            const int ki = p / 3, kj = p % 3;
            float attA0 = atts[p * 256 + yA * 16 + r4];
            float attB0 = atts[p * 256 + yA * 16 + r4 + 8];
            float attA1 = atts[p * 256 + (yA + 1) * 16 + r4];
            float attB1 = atts[p * 256 + (yA + 1) * 16 + r4 + 8];
            const ull* wbP = wsu + p * 640 + r4 * 20 + k0;
            const uint32_t* xbase0 = xsT + k0 * XN + (yA + ki) * XR + (r4 + kj) + 3;
            const uint32_t* xbase1 = xbase0 + XR;
#pragma unroll
            for (int q = 0; q < 4; q++) {
                const uint32_t* xc0 = xbase0 + q * (8 * XN);
                const uint32_t* xc1 = xbase1 + q * (8 * XN);
                uint32_t a0[4], a1[4];
                a0[0] = cvt_tf32(__uint_as_float(xc0[0]) * attA0);
                a0[1] = cvt_tf32(__uint_as_float(xc0[8]) * attB0);
                a0[2] = cvt_tf32(__uint_as_float(xc0[4 * XN]) * attA0);
                a0[3] = cvt_tf32(__uint_as_float(xc0[4 * XN + 8]) * attB0);
                a1[0] = cvt_tf32(__uint_as_float(xc1[0]) * attA1);
                a1[1] = cvt_tf32(__uint_as_float(xc1[8]) * attB1);
                a1[2] = cvt_tf32(__uint_as_float(xc1[4 * XN]) * attA1);
                a1[3] = cvt_tf32(__uint_as_float(xc1[4 * XN + 8]) * attB1);
#pragma unroll
                for (int mc = 0; mc < 4; mc++) {
                    ull wv = wbP[mc * 160 + 4 * q];
                    uint32_t bb[2] = {(uint32_t)wv, (uint32_t)(wv >> 32)};
                    mma_tf32(D[0][mc], a0, bb);
                    mma_tf32(D[1][mc], a1, bb);
                }
            }
        }

        // store
        {
#pragma unroll
            for (int f = 0; f < 2; f++) {
                int gy = y0 + yA + f;
#pragma unroll
                for (int mc = 0; mc < 4; mc++) {
                    int m = mc * 8 + 2 * k0;
                    float bv0 = sbias[th * 32 + m], bv1 = sbias[th * 32 + m + 1];
                    float* o0 = out + ((size_t)(b * 32 + m) * Hh + gy) * Ww + x0;
                    float* o1 = o0 + (size_t)Hh * Ww;
                    o0[r4]     = D[f][mc][0] + bv0;
                    o1[r4]     = D[f][mc][1] + bv1;
                    o0[r4 + 8] = D[f][mc][2] + bv0;
                    o1[r4 + 8] = D[f][mc][3] + bv1;
                }
            }
        }
    }
}

// ---------------------------------------------------------------------------
extern "C" void kernel_launch(void* const* d_in, const int* in_sizes, int n_in,
                              void* d_out, int out_size) {
    const float* x   = (const float*)d_in[0];
    const float* a1w = (const float*)d_in[1];
    const float* a1b = (const float*)d_in[2];
    const float* a2w = (const float*)d_in[3];
    const float* a2b = (const float*)d_in[4];
    const float* a3w = (const float*)d_in[5];
    const float* a3b = (const float*)d_in[6];
    const float* b1w = (const float*)d_in[7];
    const float* b1b = (const float*)d_in[8];
    const float* b2w = (const float*)d_in[9];
    const float* b2b = (const float*)d_in[10];
    const float* wgt = (const float*)d_in[11];
    float* out = (float*)d_out;

    prep_kernel<<<512, 256>>>(x);
    bias_kernel<<<1, 256>>>(b1w, b1b, b2w, b2b);

    int smF = (55680 + 64 + 81 + 81 + 9 + 9 + 9 + 3) * (int)sizeof(uint32_t);
    cudaFuncSetAttribute(fused_kernel, cudaFuncAttributeMaxDynamicSharedMemorySize, smF);
    fused_kernel<<<144, 512, smF>>>(a1w, a1b, a2w, a2b, a3w, a3b, wgt, out);
}

// round 14
// speedup vs baseline: 1.3520x; 1.0437x over previous
#include <cuda_runtime.h>
#include <cstdint>

#define Hh 192
#define Ww 192

// padded tf32-rounded copy of x: [b*32+n][194 rows][208 cols], col = gx+4, row = gy+1
#define PSTRIDE 208
#define PPLANE  40352   // 194*208
__device__ float g_xt[256 * PPLANE];
__device__ float g_part[1024];
__device__ float g_bias[8 * 32];

// xs geometry (u32): row stride 24, n-stride 456, half = 32*456
#define XR 24
#define XN 456
#define XH 14592

typedef unsigned long long ull;

__device__ __forceinline__ uint32_t cvt_tf32(float x) {
    uint32_t r; asm("cvt.rna.tf32.f32 %0, %1;" : "=r"(r) : "f"(x)); return r;
}
__device__ __forceinline__ void mma_tf32(float d[4], const uint32_t a[4], const uint32_t b[2]) {
    asm("mma.sync.aligned.m16n8k8.row.col.f32.tf32.tf32.f32 "
        "{%0,%1,%2,%3},{%4,%5,%6,%7},{%8,%9},{%0,%1,%2,%3};"
        : "+f"(d[0]), "+f"(d[1]), "+f"(d[2]), "+f"(d[3])
        : "r"(a[0]), "r"(a[1]), "r"(a[2]), "r"(a[3]), "r"(b[0]), "r"(b[1]));
}
__device__ __forceinline__ void cpasync16(uint32_t dst_sh, const void* src) {
    asm volatile("cp.async.cg.shared.global [%0], [%1], 16;" :: "r"(dst_sh), "l"(src));
}
__device__ __forceinline__ void barh(int th) {
    asm volatile("bar.sync %0, %1;" :: "r"(th + 1), "r"(256) : "memory");
}

// ---------------------------------------------------------------------------
// Kernel 1: prep — 4 CTAs per plane, 9 batched LDG.128 then cvt+store.
// ---------------------------------------------------------------------------
__global__ __launch_bounds__(256, 8)
void prep_kernel(const float* __restrict__ x) {
    int blk = blockIdx.x;
    int plane = blk >> 2, qt = blk & 3;
    const float4* src = (const float4*)(x + (size_t)plane * (Hh * Ww));
    uint32_t* dst = (uint32_t*)(g_xt + (size_t)plane * PPLANE);
    int t = threadIdx.x;

    float4 v[9];
#pragma unroll
    for (int k = 0; k < 9; k++) v[k] = src[qt * 2304 + t + k * 256];

    float s = 0.f;
#pragma unroll
    for (int k = 0; k < 9; k++) s += (v[k].x + v[k].y) + (v[k].z + v[k].w);

#pragma unroll
    for (int k = 0; k < 9; k++) {
        int i = qt * 2304 + t + k * 256;
        uint4 w;
        w.x = cvt_tf32(v[k].x); w.y = cvt_tf32(v[k].y);
        w.z = cvt_tf32(v[k].z); w.w = cvt_tf32(v[k].w);
        int gy = i / 48, gx4 = i % 48;
        *(uint4*)(dst + (gy + 1) * PSTRIDE + 4 + gx4 * 4) = w;
    }
    // padding rows: top (qt 0), bottom (qt 3)
    if (qt == 0 && t < 52)
        *(uint4*)(dst + t * 4) = make_uint4(0u, 0u, 0u, 0u);
    if (qt == 3 && t < 52)
        *(uint4*)(dst + 193 * PSTRIDE + t * 4) = make_uint4(0u, 0u, 0u, 0u);
    // side cols for this quarter's 48 rows: col4 {0, 49, 50, 51}
    for (int i = t; i < 192; i += 256) {
        int row = 1 + qt * 48 + (i >> 2);
        int c4sel = i & 3;
        int c4 = (c4sel == 0) ? 0 : (48 + c4sel);
        *(uint4*)(dst + row * PSTRIDE + c4 * 4) = make_uint4(0u, 0u, 0u, 0u);
    }

#pragma unroll
    for (int o = 16; o > 0; o >>= 1) s += __shfl_xor_sync(0xffffffffu, s, o);
    __shared__ float red[8];
    if ((t & 31) == 0) red[t >> 5] = s;
    __syncthreads();
    if (t == 0) {
        float r = 0.f;
#pragma unroll
        for (int i = 0; i < 8; i++) r += red[i];
        g_part[blk] = r;
    }
}

// ---------------------------------------------------------------------------
// Kernel 2: bias MLP.
// ---------------------------------------------------------------------------
__global__ void bias_kernel(const float* __restrict__ b1w, const float* __restrict__ b1b,
                            const float* __restrict__ b2w, const float* __restrict__ b2b) {
    __shared__ float ps[256];
    __shared__ float h[8 * 32];
    int t = threadIdx.x;
    ps[t] = (g_part[4 * t] + g_part[4 * t + 1] + g_part[4 * t + 2] + g_part[4 * t + 3])
            * (1.f / (Hh * Ww));
    __syncthreads();
    int b = t >> 5, k = t & 31;
    float s = b1b[k];
    for (int n = 0; n < 32; n++) s += ps[b * 32 + n] * b1w[k * 32 + n];
    h[t] = fmaxf(s, 0.f);
    __syncthreads();
    int m = k;
    float s2 = b2b[m];
    for (int kk = 0; kk < 32; kk++) s2 += h[b * 32 + kk] * b2w[m * 32 + kk];
    g_bias[t] = s2;
}

// ---------------------------------------------------------------------------
// Fused kernel: per-half phases; xs tf32; atts [pixel][13] (hoistable att
// loads, conflict-free epilogue writes).
// ---------------------------------------------------------------------------
__global__ __launch_bounds__(512, 1)
void fused_kernel(const float* __restrict__ a1w, const float* __restrict__ a1b,
                  const float* __restrict__ a2w, const float* __restrict__ a2b,
                  const float* __restrict__ a3w, const float* __restrict__ a3b,
                  const float* __restrict__ weight, float* __restrict__ out) {
    extern __shared__ uint32_t smu[];
    uint32_t* xs = smu;                     // 2 * XH = 29184 (tf32 bits)
    uint32_t* w1t2 = smu + 29184;           // 5760
    uint32_t* ws2 = smu + 34944;            // 11520
    uint32_t* trbase = smu + 46464;         // 2 * 4608 (tr ull / atts [px][13] overlay: 3328 u32)
    float* sbias = (float*)(smu + 55680);   // 64
    float* w2 = sbias + 64;                 // 81
    float* w3 = w2 + 81;                    // 81
    float* bb1 = w3 + 81;                   // 9
    float* bb2 = bb1 + 9;                   // 9
    float* bb3 = bb2 + 9;                   // 9

    int tid = threadIdx.x;
    uint32_t xs_sh = (uint32_t)__cvta_generic_to_shared(xs);

    for (int i = tid; i < 5760; i += 512) {
        int t = i / 640;
        int r = i % 640;
        int o = r / 40, c = r % 40;
        int pair = c >> 1, e = c & 1;
        uint32_t v = 0u;
        if (o < 9 && pair < 16) {
            int n = 8 * (pair >> 2) + (pair & 3) + 4 * e;
            v = cvt_tf32(a1w[o * 288 + n * 9 + t]);
        }
        w1t2[i] = v;
    }
    for (int i = tid; i < 11520; i += 512) {
        int p = i / 1280;
        int r = i % 1280;
        int m = r / 40, c = r % 40;
        int pair = c >> 1, e = c & 1;
        uint32_t v = 0u;
        if (pair < 16) {
            int n = 8 * (pair >> 2) + (pair & 3) + 4 * e;
            v = cvt_tf32(weight[(m * 32 + n) * 9 + p]);
        }
        ws2[i] = v;
    }
    if (tid < 81) { w2[tid] = a2w[tid]; w3[tid] = a3w[tid]; }
    if (tid < 9) { bb1[tid] = a1b[tid]; bb2[tid] = a2b[tid]; bb3[tid] = a3b[tid]; }
    __syncthreads();

    int wid = tid >> 5, lane = tid & 31;
    int r4 = lane >> 2, k0 = lane & 3;
    int th = wid >> 3;
    int tloc = tid & 255;
    int yA = 2 * (wid & 7);

    const ull* w1u = (const ull*)w1t2;
    const ull* wsu = (const ull*)ws2;
    const uint32_t* xsT = xs + th * XH;

    for (int it = 0; it < 4; it++) {
        int pairIdx = blockIdx.x * 4 + it;
        int b = pairIdx / 72;
        int rr = pairIdx % 72;
        int y0 = (rr / 6) * 16;
        int x0 = (rr % 6) * 32 + th * 16;

        barh(th);

        for (int r = tloc; r < 576; r += 256) {
            int n = r / 18, yy = r - n * 18;
            const float* src = g_xt + (size_t)(b * 32 + n) * PPLANE + (y0 + yy) * PSTRIDE + x0;
            uint32_t dsh = xs_sh + 4u * (th * XH + n * XN + yy * XR);
#pragma unroll
            for (int k = 0; k < 6; k++) cpasync16(dsh + 16 * k, src + 4 * k);
        }
        asm volatile("cp.async.commit_group;");
        if (tloc < 32) sbias[th * 32 + tloc] = g_bias[b * 32 + tloc];
        asm volatile("cp.async.wait_group 0;");
        barh(th);

        // ---- attention mainloop ----
        float DA[2][2][4];
#pragma unroll
        for (int f = 0; f < 2; f++)
#pragma unroll
            for (int oc = 0; oc < 2; oc++)
#pragma unroll
                for (int e = 0; e < 4; e++) DA[f][oc][e] = 0.f;

#pragma unroll
        for (int t = 0; t < 9; t++) {
            const int ki = t / 3, kj = t % 3;
            const ull* wbT = w1u + t * 320 + r4 * 20 + k0;
            const uint32_t* xbase0 = xsT + k0 * XN + (yA + ki) * XR + (r4 + kj) + 3;
            const uint32_t* xbase1 = xbase0 + XR;
#pragma unroll
            for (int q = 0; q < 4; q++) {
                const uint32_t* xc0 = xbase0 + q * (8 * XN);
                const uint32_t* xc1 = xbase1 + q * (8 * XN);
                uint32_t a0[4] = {xc0[0], xc0[8], xc0[4 * XN], xc0[4 * XN + 8]};
                uint32_t a1[4] = {xc1[0], xc1[8], xc1[4 * XN], xc1[4 * XN + 8]};
#pragma unroll
                for (int oc = 0; oc < 2; oc++) {
                    ull wv = wbT[oc * 160 + 4 * q];
                    uint32_t bb[2] = {(uint32_t)wv, (uint32_t)(wv >> 32)};
                    mma_tf32(DA[0][oc], a0, bb);
                    mma_tf32(DA[1][oc], a1, bb);
                }
            }
        }

        // transpose DA -> tr
        {
            ull* tr = (ull*)(trbase + th * 4608);
#pragma unroll
            for (int f = 0; f < 2; f++) {
                int yy = yA + f;
#pragma unroll
                for (int oc = 0; oc < 2; oc++) {
                    int pr = oc * 4 + k0;
                    float2 lo2 = make_float2(DA[f][oc][0], DA[f][oc][1]);
                    float2 hi2 = make_float2(DA[f][oc][2], DA[f][oc][3]);
                    tr[(yy * 16 + r4) * 9 + pr]     = *(ull*)&lo2;
                    tr[(yy * 16 + r4 + 8) * 9 + pr] = *(ull*)&hi2;
                }
            }
        }
        barh(th);

        // attention epilogue; atts overlays tr, layout [px][13]
        {
            int px = tloc;
            const ull* trt = (const ull*)(trbase + th * 4608);
            float u[10], z[9], att[9];
#pragma unroll
            for (int j = 0; j < 5; j++) {
                float2 v = *(float2*)&trt[px * 9 + j];
                u[2 * j] = v.x;
                u[2 * j + 1] = v.y;
            }
#pragma unroll
            for (int o = 0; o < 9; o++) u[o] = fmaxf(u[o] + bb1[o], 0.f);
#pragma unroll
            for (int o2 = 0; o2 < 9; o2++) {
                float s = bb2[o2];
#pragma unroll
                for (int o = 0; o < 9; o++) s += w2[o2 * 9 + o] * u[o];
                z[o2] = fmaxf(s, 0.f);
            }
#pragma unroll
            for (int o3 = 0; o3 < 9; o3++) {
                float s = bb3[o3];
#pragma unroll
                for (int o2 = 0; o2 < 9; o2++) s += w3[o3 * 9 + o2] * z[o2];
                att[o3] = 1.f / (1.f + __expf(-s));
            }
            barh(th);
            float* atts_t = (float*)(trbase + th * 4608);
#pragma unroll
            for (int o3 = 0; o3 < 9; o3++) atts_t[px * 13 + o3] = att[o3];
        }
        barh(th);

        // ---- main mainloop ----
        const float* atts = (const float*)(trbase + th * 4608);
        // hoist all attention values for this thread's 4 pixel-slots
        float attv[4][9];
        {
            const float* pA0 = atts + (yA * 16 + r4) * 13;
            const float* pB0 = atts + (yA * 16 + r4 + 8) * 13;
            const float* pA1 = atts + ((yA + 1) * 16 + r4) * 13;
            const float* pB1 = atts + ((yA + 1) * 16 + r4 + 8) * 13;
#pragma unroll
            for (int p = 0; p < 9; p++) {
                attv[0][p] = pA0[p];
                attv[1][p] = pB0[p];
                attv[2][p] = pA1[p];
                attv[3][p] = pB1[p];
            }
        }
        float D[2][4][4];
#pragma unroll
        for (int f = 0; f < 2; f++)
#pragma unroll
            for (int mc = 0; mc < 4; mc++)
#pragma unroll
                for (int e = 0; e < 4; e++) D[f][mc][e] = 0.f;

#pragma unroll
        for (int p = 0; p < 9; p++) {
            const int ki = p / 3, kj = p % 3;
            float attA0 = attv[0][p], attB0 = attv[1][p];
            float attA1 = attv[2][p], attB1 = attv[3][p];
            const ull* wbP = wsu + p * 640 + r4 * 20 + k0;
            const uint32_t* xbase0 = xsT + k0 * XN + (yA + ki) * XR + (r4 + kj) + 3;
            const uint32_t* xbase1 = xbase0 + XR;
#pragma unroll
            for (int q = 0; q < 4; q++) {
                const uint32_t* xc0 = xbase0 + q * (8 * XN);
                const uint32_t* xc1 = xbase1 + q * (8 * XN);
                uint32_t a0[4], a1[4];
                a0[0] = cvt_tf32(__uint_as_float(xc0[0]) * attA0);
                a0[1] = cvt_tf32(__uint_as_float(xc0[8]) * attB0);
                a0[2] = cvt_tf32(__uint_as_float(xc0[4 * XN]) * attA0);
                a0[3] = cvt_tf32(__uint_as_float(xc0[4 * XN + 8]) * attB0);
                a1[0] = cvt_tf32(__uint_as_float(xc1[0]) * attA1);
                a1[1] = cvt_tf32(__uint_as_float(xc1[8]) * attB1);
                a1[2] = cvt_tf32(__uint_as_float(xc1[4 * XN]) * attA1);
                a1[3] = cvt_tf32(__uint_as_float(xc1[4 * XN + 8]) * attB1);
#pragma unroll
                for (int mc = 0; mc < 4; mc++) {
                    ull wv = wbP[mc * 160 + 4 * q];
                    uint32_t bb[2] = {(uint32_t)wv, (uint32_t)(wv >> 32)};
                    mma_tf32(D[0][mc], a0, bb);
                    mma_tf32(D[1][mc], a1, bb);
                }
            }
        }

        // store
        {
#pragma unroll
            for (int f = 0; f < 2; f++) {
                int gy = y0 + yA + f;
#pragma unroll
                for (int mc = 0; mc < 4; mc++) {
                    int m = mc * 8 + 2 * k0;
                    float bv0 = sbias[th * 32 + m], bv1 = sbias[th * 32 + m + 1];
                    float* o0 = out + ((size_t)(b * 32 + m) * Hh + gy) * Ww + x0;
                    float* o1 = o0 + (size_t)Hh * Ww;
                    o0[r4]     = D[f][mc][0] + bv0;
                    o1[r4]     = D[f][mc][1] + bv1;
                    o0[r4 + 8] = D[f][mc][2] + bv0;
                    o1[r4 + 8] = D[f][mc][3] + bv1;
                }
            }
        }
    }
}

// ---------------------------------------------------------------------------
extern "C" void kernel_launch(void* const* d_in, const int* in_sizes, int n_in,
                              void* d_out, int out_size) {
    const float* x   = (const float*)d_in[0];
    const float* a1w = (const float*)d_in[1];
    const float* a1b = (const float*)d_in[2];
    const float* a2w = (const float*)d_in[3];
    const float* a2b = (const float*)d_in[4];
    const float* a3w = (const float*)d_in[5];
    const float* a3b = (const float*)d_in[6];
    const float* b1w = (const float*)d_in[7];
    const float* b1b = (const float*)d_in[8];
    const float* b2w = (const float*)d_in[9];
    const float* b2b = (const float*)d_in[10];
    const float* wgt = (const float*)d_in[11];
    float* out = (float*)d_out;

    prep_kernel<<<1024, 256>>>(x);
    bias_kernel<<<1, 256>>>(b1w, b1b, b2w, b2b);

    int smF = (55680 + 64 + 81 + 81 + 9 + 9 + 9 + 3) * (int)sizeof(uint32_t);
    cudaFuncSetAttribute(fused_kernel, cudaFuncAttributeMaxDynamicSharedMemorySize, smF);
    fused_kernel<<<144, 512, smF>>>(a1w, a1b, a2w, a2b, a3w, a3b, wgt, out);
}

// round 15
// speedup vs baseline: 1.3806x; 1.0212x over previous
#include <cuda_runtime.h>
#include <cstdint>

#define Hh 192
#define Ww 192

// padded tf32-rounded copy of x: [b*32+n][194 rows][208 cols], col = gx+4, row = gy+1
#define PSTRIDE 208
#define PPLANE  40352   // 194*208
__device__ float g_xt[256 * PPLANE];
__device__ float g_part[1024];
__device__ float g_bias[8 * 32];

// xs geometry (u32): row stride 24, n-stride 456, half = 32*456
#define XR 24
#define XN 456
#define XH 14592

typedef unsigned long long ull;

__device__ __forceinline__ uint32_t cvt_tf32(float x) {
    uint32_t r; asm("cvt.rna.tf32.f32 %0, %1;" : "=r"(r) : "f"(x)); return r;
}
__device__ __forceinline__ void mma_tf32(float d[4], const uint32_t a[4], const uint32_t b[2]) {
    asm("mma.sync.aligned.m16n8k8.row.col.f32.tf32.tf32.f32 "
        "{%0,%1,%2,%3},{%4,%5,%6,%7},{%8,%9},{%0,%1,%2,%3};"
        : "+f"(d[0]), "+f"(d[1]), "+f"(d[2]), "+f"(d[3])
        : "r"(a[0]), "r"(a[1]), "r"(a[2]), "r"(a[3]), "r"(b[0]), "r"(b[1]));
}
// init form: d = a*b + z (z = persistent zero quad, d != z) — avoids G zero-fill MOVs
__device__ __forceinline__ void mma_tf32_z(float d[4], const uint32_t a[4], const uint32_t b[2],
                                           const float z[4]) {
    asm("mma.sync.aligned.m16n8k8.row.col.f32.tf32.tf32.f32 "
        "{%0,%1,%2,%3},{%4,%5,%6,%7},{%8,%9},{%10,%11,%12,%13};"
        : "=f"(d[0]), "=f"(d[1]), "=f"(d[2]), "=f"(d[3])
        : "r"(a[0]), "r"(a[1]), "r"(a[2]), "r"(a[3]), "r"(b[0]), "r"(b[1]),
          "f"(z[0]), "f"(z[1]), "f"(z[2]), "f"(z[3]));
}
__device__ __forceinline__ void cpasync16(uint32_t dst_sh, const void* src) {
    asm volatile("cp.async.cg.shared.global [%0], [%1], 16;" :: "r"(dst_sh), "l"(src));
}
__device__ __forceinline__ void barh(int th) {
    asm volatile("bar.sync %0, %1;" :: "r"(th + 1), "r"(256) : "memory");
}

// ---------------------------------------------------------------------------
// Kernel 1: prep — 4 CTAs per plane, 9 batched LDG.128 then cvt+store.
// ---------------------------------------------------------------------------
__global__ __launch_bounds__(256, 8)
void prep_kernel(const float* __restrict__ x) {
    int blk = blockIdx.x;
    int plane = blk >> 2, qt = blk & 3;
    const float4* src = (const float4*)(x + (size_t)plane * (Hh * Ww));
    uint32_t* dst = (uint32_t*)(g_xt + (size_t)plane * PPLANE);
    int t = threadIdx.x;

    float4 v[9];
#pragma unroll
    for (int k = 0; k < 9; k++) v[k] = src[qt * 2304 + t + k * 256];

    float s = 0.f;
#pragma unroll
    for (int k = 0; k < 9; k++) s += (v[k].x + v[k].y) + (v[k].z + v[k].w);

#pragma unroll
    for (int k = 0; k < 9; k++) {
        int i = qt * 2304 + t + k * 256;
        uint4 w;
        w.x = cvt_tf32(v[k].x); w.y = cvt_tf32(v[k].y);
        w.z = cvt_tf32(v[k].z); w.w = cvt_tf32(v[k].w);
        int gy = i / 48, gx4 = i % 48;
        *(uint4*)(dst + (gy + 1) * PSTRIDE + 4 + gx4 * 4) = w;
    }
    if (qt == 0 && t < 52)
        *(uint4*)(dst + t * 4) = make_uint4(0u, 0u, 0u, 0u);
    if (qt == 3 && t < 52)
        *(uint4*)(dst + 193 * PSTRIDE + t * 4) = make_uint4(0u, 0u, 0u, 0u);
    for (int i = t; i < 192; i += 256) {
        int row = 1 + qt * 48 + (i >> 2);
        int c4sel = i & 3;
        int c4 = (c4sel == 0) ? 0 : (48 + c4sel);
        *(uint4*)(dst + row * PSTRIDE + c4 * 4) = make_uint4(0u, 0u, 0u, 0u);
    }

#pragma unroll
    for (int o = 16; o > 0; o >>= 1) s += __shfl_xor_sync(0xffffffffu, s, o);
    __shared__ float red[8];
    if ((t & 31) == 0) red[t >> 5] = s;
    __syncthreads();
    if (t == 0) {
        float r = 0.f;
#pragma unroll
        for (int i = 0; i < 8; i++) r += red[i];
        g_part[blk] = r;
    }
}

// ---------------------------------------------------------------------------
// Kernel 2: bias MLP.
// ---------------------------------------------------------------------------
__global__ void bias_kernel(const float* __restrict__ b1w, const float* __restrict__ b1b,
                            const float* __restrict__ b2w, const float* __restrict__ b2b) {
    __shared__ float ps[256];
    __shared__ float h[8 * 32];
    int t = threadIdx.x;
    ps[t] = (g_part[4 * t] + g_part[4 * t + 1] + g_part[4 * t + 2] + g_part[4 * t + 3])
            * (1.f / (Hh * Ww));
    __syncthreads();
    int b = t >> 5, k = t & 31;
    float s = b1b[k];
    for (int n = 0; n < 32; n++) s += ps[b * 32 + n] * b1w[k * 32 + n];
    h[t] = fmaxf(s, 0.f);
    __syncthreads();
    int m = k;
    float s2 = b2b[m];
    for (int kk = 0; kk < 32; kk++) s2 += h[b * 32 + kk] * b2w[m * 32 + kk];
    g_bias[t] = s2;
}

// ---------------------------------------------------------------------------
// Fused kernel: per-half phases; xs tf32; main loop = pure LDS->MMA with
// post-MMA exact-fp32 attention merge (G zero-init via MMA C-operand).
// ---------------------------------------------------------------------------
__global__ __launch_bounds__(512, 1)
void fused_kernel(const float* __restrict__ a1w, const float* __restrict__ a1b,
                  const float* __restrict__ a2w, const float* __restrict__ a2b,
                  const float* __restrict__ a3w, const float* __restrict__ a3b,
                  const float* __restrict__ weight, float* __restrict__ out) {
    extern __shared__ uint32_t smu[];
    uint32_t* xs = smu;                     // 2 * XH = 29184 (tf32 bits)
    uint32_t* w1t2 = smu + 29184;           // 5760
    uint32_t* ws2 = smu + 34944;            // 11520
    uint32_t* trbase = smu + 46464;         // 2 * 4608 (tr ull / atts [px][13] overlay)
    float* sbias = (float*)(smu + 55680);   // 64
    float* w2 = sbias + 64;                 // 81
    float* w3 = w2 + 81;                    // 81
    float* bb1 = w3 + 81;                   // 9
    float* bb2 = bb1 + 9;                   // 9
    float* bb3 = bb2 + 9;                   // 9

    int tid = threadIdx.x;
    uint32_t xs_sh = (uint32_t)__cvta_generic_to_shared(xs);

    for (int i = tid; i < 5760; i += 512) {
        int t = i / 640;
        int r = i % 640;
        int o = r / 40, c = r % 40;
        int pair = c >> 1, e = c & 1;
        uint32_t v = 0u;
        if (o < 9 && pair < 16) {
            int n = 8 * (pair >> 2) + (pair & 3) + 4 * e;
            v = cvt_tf32(a1w[o * 288 + n * 9 + t]);
        }
        w1t2[i] = v;
    }
    for (int i = tid; i < 11520; i += 512) {
        int p = i / 1280;
        int r = i % 1280;
        int m = r / 40, c = r % 40;
        int pair = c >> 1, e = c & 1;
        uint32_t v = 0u;
        if (pair < 16) {
            int n = 8 * (pair >> 2) + (pair & 3) + 4 * e;
            v = cvt_tf32(weight[(m * 32 + n) * 9 + p]);
        }
        ws2[i] = v;
    }
    if (tid < 81) { w2[tid] = a2w[tid]; w3[tid] = a3w[tid]; }
    if (tid < 9) { bb1[tid] = a1b[tid]; bb2[tid] = a2b[tid]; bb3[tid] = a3b[tid]; }
    __syncthreads();

    int wid = tid >> 5, lane = tid & 31;
    int r4 = lane >> 2, k0 = lane & 3;
    int th = wid >> 3;
    int tloc = tid & 255;
    int yA = 2 * (wid & 7);

    const ull* w1u = (const ull*)w1t2;
    const ull* wsu = (const ull*)ws2;
    const uint32_t* xsT = xs + th * XH;

    const float zq[4] = {0.f, 0.f, 0.f, 0.f};

    for (int it = 0; it < 4; it++) {
        int pairIdx = blockIdx.x * 4 + it;
        int b = pairIdx / 72;
        int rr = pairIdx % 72;
        int y0 = (rr / 6) * 16;
        int x0 = (rr % 6) * 32 + th * 16;

        barh(th);

        for (int r = tloc; r < 576; r += 256) {
            int n = r / 18, yy = r - n * 18;
            const float* src = g_xt + (size_t)(b * 32 + n) * PPLANE + (y0 + yy) * PSTRIDE + x0;
            uint32_t dsh = xs_sh + 4u * (th * XH + n * XN + yy * XR);
#pragma unroll
            for (int k = 0; k < 6; k++) cpasync16(dsh + 16 * k, src + 4 * k);
        }
        asm volatile("cp.async.commit_group;");
        if (tloc < 32) sbias[th * 32 + tloc] = g_bias[b * 32 + tloc];
        asm volatile("cp.async.wait_group 0;");
        barh(th);

        // ---- attention mainloop ----
        float DA[2][2][4];
#pragma unroll
        for (int f = 0; f < 2; f++)
#pragma unroll
            for (int oc = 0; oc < 2; oc++)
#pragma unroll
                for (int e = 0; e < 4; e++) DA[f][oc][e] = 0.f;

#pragma unroll
        for (int t = 0; t < 9; t++) {
            const int ki = t / 3, kj = t % 3;
            const ull* wbT = w1u + t * 320 + r4 * 20 + k0;
            const uint32_t* xbase0 = xsT + k0 * XN + (yA + ki) * XR + (r4 + kj) + 3;
            const uint32_t* xbase1 = xbase0 + XR;
#pragma unroll
            for (int q = 0; q < 4; q++) {
                const uint32_t* xc0 = xbase0 + q * (8 * XN);
                const uint32_t* xc1 = xbase1 + q * (8 * XN);
                uint32_t a0[4] = {xc0[0], xc0[8], xc0[4 * XN], xc0[4 * XN + 8]};
                uint32_t a1[4] = {xc1[0], xc1[8], xc1[4 * XN], xc1[4 * XN + 8]};
#pragma unroll
                for (int oc = 0; oc < 2; oc++) {
                    ull wv = wbT[oc * 160 + 4 * q];
                    uint32_t bb[2] = {(uint32_t)wv, (uint32_t)(wv >> 32)};
                    mma_tf32(DA[0][oc], a0, bb);
                    mma_tf32(DA[1][oc], a1, bb);
                }
            }
        }

        // transpose DA -> tr
        {
            ull* tr = (ull*)(trbase + th * 4608);
#pragma unroll
            for (int f = 0; f < 2; f++) {
                int yy = yA + f;
#pragma unroll
                for (int oc = 0; oc < 2; oc++) {
                    int pr = oc * 4 + k0;
                    float2 lo2 = make_float2(DA[f][oc][0], DA[f][oc][1]);
                    float2 hi2 = make_float2(DA[f][oc][2], DA[f][oc][3]);
                    tr[(yy * 16 + r4) * 9 + pr]     = *(ull*)&lo2;
                    tr[(yy * 16 + r4 + 8) * 9 + pr] = *(ull*)&hi2;
                }
            }
        }
        barh(th);

        // attention epilogue; atts overlays tr, layout [px][13]
        {
            int px = tloc;
            const ull* trt = (const ull*)(trbase + th * 4608);
            float u[10], z[9], att[9];
#pragma unroll
            for (int j = 0; j < 5; j++) {
                float2 v = *(float2*)&trt[px * 9 + j];
                u[2 * j] = v.x;
                u[2 * j + 1] = v.y;
            }
#pragma unroll
            for (int o = 0; o < 9; o++) u[o] = fmaxf(u[o] + bb1[o], 0.f);
#pragma unroll
            for (int o2 = 0; o2 < 9; o2++) {
                float s = bb2[o2];
#pragma unroll
                for (int o = 0; o < 9; o++) s += w2[o2 * 9 + o] * u[o];
                z[o2] = fmaxf(s, 0.f);
            }
#pragma unroll
            for (int o3 = 0; o3 < 9; o3++) {
                float s = bb3[o3];
#pragma unroll
                for (int o2 = 0; o2 < 9; o2++) s += w3[o3 * 9 + o2] * z[o2];
                att[o3] = 1.f / (1.f + __expf(-s));
            }
            barh(th);
            float* atts_t = (float*)(trbase + th * 4608);
#pragma unroll
            for (int o3 = 0; o3 < 9; o3++) atts_t[px * 13 + o3] = att[o3];
        }
        barh(th);

        // ---- main mainloop: pure LDS->MMA into G, exact fp32 att merge ----
        const float* atts = (const float*)(trbase + th * 4608);
        float D[2][4][4];
#pragma unroll
        for (int f = 0; f < 2; f++)
#pragma unroll
            for (int mc = 0; mc < 4; mc++)
#pragma unroll
                for (int e = 0; e < 4; e++) D[f][mc][e] = 0.f;

#pragma unroll
        for (int p = 0; p < 9; p++) {
            const int ki = p / 3, kj = p % 3;
            float G[2][4][4];
            const ull* wbP = wsu + p * 640 + r4 * 20 + k0;
            const uint32_t* xbase0 = xsT + k0 * XN + (yA + ki) * XR + (r4 + kj) + 3;
            const uint32_t* xbase1 = xbase0 + XR;
            // q = 0: init G through MMA C-operand (no zero-fill MOVs)
            {
                const uint32_t* xc0 = xbase0;
                const uint32_t* xc1 = xbase1;
                uint32_t a0[4] = {xc0[0], xc0[8], xc0[4 * XN], xc0[4 * XN + 8]};
                uint32_t a1[4] = {xc1[0], xc1[8], xc1[4 * XN], xc1[4 * XN + 8]};
#pragma unroll
                for (int mc = 0; mc < 4; mc++) {
                    ull wv = wbP[mc * 160];
                    uint32_t bb[2] = {(uint32_t)wv, (uint32_t)(wv >> 32)};
                    mma_tf32_z(G[0][mc], a0, bb, zq);
                    mma_tf32_z(G[1][mc], a1, bb, zq);
                }
            }
#pragma unroll
            for (int q = 1; q < 4; q++) {
                const uint32_t* xc0 = xbase0 + q * (8 * XN);
                const uint32_t* xc1 = xbase1 + q * (8 * XN);
                uint32_t a0[4] = {xc0[0], xc0[8], xc0[4 * XN], xc0[4 * XN + 8]};
                uint32_t a1[4] = {xc1[0], xc1[8], xc1[4 * XN], xc1[4 * XN + 8]};
#pragma unroll
                for (int mc = 0; mc < 4; mc++) {
                    ull wv = wbP[mc * 160 + 4 * q];
                    uint32_t bb[2] = {(uint32_t)wv, (uint32_t)(wv >> 32)};
                    mma_tf32(G[0][mc], a0, bb);
                    mma_tf32(G[1][mc], a1, bb);
                }
            }
            // exact fp32 attention merge
            float attA0 = atts[(yA * 16 + r4) * 13 + p];
            float attB0 = atts[(yA * 16 + r4 + 8) * 13 + p];
            float attA1 = atts[((yA + 1) * 16 + r4) * 13 + p];
            float attB1 = atts[((yA + 1) * 16 + r4 + 8) * 13 + p];
#pragma unroll
            for (int mc = 0; mc < 4; mc++) {
                D[0][mc][0] += attA0 * G[0][mc][0];
                D[0][mc][1] += attA0 * G[0][mc][1];
                D[0][mc][2] += attB0 * G[0][mc][2];
                D[0][mc][3] += attB0 * G[0][mc][3];
                D[1][mc][0] += attA1 * G[1][mc][0];
                D[1][mc][1] += attA1 * G[1][mc][1];
                D[1][mc][2] += attB1 * G[1][mc][2];
                D[1][mc][3] += attB1 * G[1][mc][3];
            }
        }

        // store
        {
#pragma unroll
            for (int f = 0; f < 2; f++) {
                int gy = y0 + yA + f;
#pragma unroll
                for (int mc = 0; mc < 4; mc++) {
                    int m = mc * 8 + 2 * k0;
                    float bv0 = sbias[th * 32 + m], bv1 = sbias[th * 32 + m + 1];
                    float* o0 = out + ((size_t)(b * 32 + m) * Hh + gy) * Ww + x0;
                    float* o1 = o0 + (size_t)Hh * Ww;
                    o0[r4]     = D[f][mc][0] + bv0;
                    o1[r4]     = D[f][mc][1] + bv1;
                    o0[r4 + 8] = D[f][mc][2] + bv0;
                    o1[r4 + 8] = D[f][mc][3] + bv1;
                }
            }
        }
    }
}

// ---------------------------------------------------------------------------
extern "C" void kernel_launch(void* const* d_in, const int* in_sizes, int n_in,
                              void* d_out, int out_size) {
    const float* x   = (const float*)d_in[0];
    const float* a1w = (const float*)d_in[1];
    const float* a1b = (const float*)d_in[2];
    const float* a2w = (const float*)d_in[3];
    const float* a2b = (const float*)d_in[4];
    const float* a3w = (const float*)d_in[5];
    const float* a3b = (const float*)d_in[6];
    const float* b1w = (const float*)d_in[7];
    const float* b1b = (const float*)d_in[8];
    const float* b2w = (const float*)d_in[9];
    const float* b2b = (const float*)d_in[10];
    const float* wgt = (const float*)d_in[11];
    float* out = (float*)d_out;

    prep_kernel<<<1024, 256>>>(x);
    bias_kernel<<<1, 256>>>(b1w, b1b, b2w, b2b);

    int smF = (55680 + 64 + 81 + 81 + 9 + 9 + 9 + 3) * (int)sizeof(uint32_t);
    cudaFuncSetAttribute(fused_kernel, cudaFuncAttributeMaxDynamicSharedMemorySize, smF);
    fused_kernel<<<144, 512, smF>>>(a1w, a1b, a2w, a2b, a3w, a3b, wgt, out);
}